// round 3
// baseline (speedup 1.0000x reference)
#include <cuda_runtime.h>
#include <cuda_bf16.h>
#include <math.h>

#define N_NODES 50000
#define N_EDGES 800000
#define HID     128
#define N_GRAPHS 64

// ---------------- scratch (allocation-free: __device__ globals) ----------------
__device__ float d_S [N_NODES * HID];   // GEMM output / scatter source
__device__ float d_G1[N_NODES * HID];
__device__ float d_G2[N_NODES * HID];
__device__ float d_G3[N_NODES * HID];
__device__ float d_T [N_NODES];         // h @ wa per node
__device__ float d_SC[N_NODES];         // aggregated attention score -> tanh
__device__ float d_POOL[N_GRAPHS * 6 * HID];

// ---------------- GEMM: out[nrows,128] = X[nrows,128] @ W[128,128] ----------------
// 128x128 output tile per block, 256 threads, 8x8 register blocking, K chunked by 32.
__global__ __launch_bounds__(256) void gemm128(const float* __restrict__ X,
                                               const float* __restrict__ W,
                                               float* __restrict__ out, int nrows)
{
    __shared__ float As[32 * 133];   // [kk][row], pad 133 -> conflict-free transposed store
    __shared__ float Bs[32 * 128];   // [kk][col]

    const int tid  = threadIdx.x;
    const int row0 = blockIdx.x * 128;
    const int tr   = tid >> 4;   // 0..15  (row group of 8)
    const int tc   = tid & 15;   // 0..15  (col group of 8)

    float acc[8][8];
#pragma unroll
    for (int i = 0; i < 8; ++i)
#pragma unroll
        for (int j = 0; j < 8; ++j) acc[i][j] = 0.f;

    for (int kc = 0; kc < 128; kc += 32) {
        __syncthreads();
#pragma unroll
        for (int it = 0; it < 16; ++it) {
            int idx = it * 256 + tid;          // 0..4095
            int r   = idx >> 5;                // 0..127
            int kk  = idx & 31;                // 0..31
            int gr  = row0 + r;
            As[kk * 133 + r] = (gr < nrows) ? X[gr * 128 + kc + kk] : 0.f;
            Bs[idx] = W[kc * 128 + idx];       // Bs[kk][c] = W[kc+kk][c]
        }
        __syncthreads();
#pragma unroll
        for (int kk = 0; kk < 32; ++kk) {
            float a[8];
#pragma unroll
            for (int i = 0; i < 8; ++i) a[i] = As[kk * 133 + tr * 8 + i];
            float4 b0 = *(const float4*)&Bs[kk * 128 + tc * 8];
            float4 b1 = *(const float4*)&Bs[kk * 128 + tc * 8 + 4];
            float b[8] = {b0.x, b0.y, b0.z, b0.w, b1.x, b1.y, b1.z, b1.w};
#pragma unroll
            for (int i = 0; i < 8; ++i)
#pragma unroll
                for (int j = 0; j < 8; ++j) acc[i][j] = fmaf(a[i], b[j], acc[i][j]);
        }
    }

#pragma unroll
    for (int i = 0; i < 8; ++i) {
        int gr = row0 + tr * 8 + i;
        if (gr < nrows) {
            float4 v0 = make_float4(acc[i][0], acc[i][1], acc[i][2], acc[i][3]);
            float4 v1 = make_float4(acc[i][4], acc[i][5], acc[i][6], acc[i][7]);
            *(float4*)&out[gr * 128 + tc * 8]     = v0;
            *(float4*)&out[gr * 128 + tc * 8 + 4] = v1;
        }
    }
}

// ---------------- edge scatter: agg[dst] += w_e * S[src], 1 warp / edge ----------------
__global__ __launch_bounds__(256) void scatter128(const int* __restrict__ src,
                                                  const int* __restrict__ dst,
                                                  const float* __restrict__ ew,
                                                  const float* __restrict__ S,
                                                  float* __restrict__ agg)
{
    int gt   = blockIdx.x * blockDim.x + threadIdx.x;
    int e    = gt >> 5;
    int lane = gt & 31;
    if (e >= N_EDGES) return;

    float w = ew[e];
    int   s = src[e];
    int   d = dst[e];

    float4 v = ((const float4*)(S + (size_t)s * 128))[lane];
    float4 r = make_float4(v.x * w, v.y * w, v.z * w, v.w * w);
    float* p = agg + (size_t)d * 128 + lane * 4;
    asm volatile("red.global.add.v4.f32 [%0], {%1,%2,%3,%4};"
                 :: "l"(p), "f"(r.x), "f"(r.y), "f"(r.z), "f"(r.w) : "memory");
}

// ---------------- g = relu(agg + b) in place (float4) ----------------
__global__ __launch_bounds__(256) void bias_relu(float* __restrict__ g,
                                                 const float* __restrict__ b)
{
    int idx = blockIdx.x * blockDim.x + threadIdx.x;   // float4 index
    if (idx >= N_NODES * 32) return;
    int c = (idx & 31) * 4;
    float4 v = ((float4*)g)[idx];
    v.x = fmaxf(v.x + b[c + 0], 0.f);
    v.y = fmaxf(v.y + b[c + 1], 0.f);
    v.z = fmaxf(v.z + b[c + 2], 0.f);
    v.w = fmaxf(v.w + b[c + 3], 0.f);
    ((float4*)g)[idx] = v;
}

// ---------------- t[node] = h[node,:] @ wa  (h = [g1|g2|g3]), 1 warp/node ----------------
__global__ __launch_bounds__(256) void att_t(const float* __restrict__ g1,
                                             const float* __restrict__ g2,
                                             const float* __restrict__ g3,
                                             const float* __restrict__ wa,
                                             float* __restrict__ t)
{
    int gt   = blockIdx.x * blockDim.x + threadIdx.x;
    int node = gt >> 5;
    int lane = gt & 31;
    if (node >= N_NODES) return;

    float4 a1 = ((const float4*)(g1 + (size_t)node * 128))[lane];
    float4 a2 = ((const float4*)(g2 + (size_t)node * 128))[lane];
    float4 a3 = ((const float4*)(g3 + (size_t)node * 128))[lane];
    float4 w1 = ((const float4*)wa)[lane];
    float4 w2 = ((const float4*)wa)[32 + lane];
    float4 w3 = ((const float4*)wa)[64 + lane];

    float s = a1.x * w1.x + a1.y * w1.y + a1.z * w1.z + a1.w * w1.w
            + a2.x * w2.x + a2.y * w2.y + a2.z * w2.z + a2.w * w2.w
            + a3.x * w3.x + a3.y * w3.y + a3.z * w3.z + a3.w * w3.w;
#pragma unroll
    for (int off = 16; off; off >>= 1) s += __shfl_xor_sync(0xFFFFFFFFu, s, off);
    if (lane == 0) t[node] = s;
}

// ---------------- sc[dst] += w_e * t[src] ----------------
__global__ __launch_bounds__(256) void scatter_scalar(const int* __restrict__ src,
                                                      const int* __restrict__ dst,
                                                      const float* __restrict__ ew,
                                                      const float* __restrict__ t,
                                                      float* __restrict__ sc)
{
    int e = blockIdx.x * blockDim.x + threadIdx.x;
    if (e >= N_EDGES) return;
    atomicAdd(&sc[dst[e]], ew[e] * t[src[e]]);
}

// ---------------- sc[i] = tanh(sc[i] + ba) ----------------
__global__ __launch_bounds__(256) void score_k(float* __restrict__ sc,
                                               const float* __restrict__ ba)
{
    int i = blockIdx.x * blockDim.x + threadIdx.x;
    if (i >= N_NODES) return;
    sc[i] = tanhf(sc[i] + ba[0]);
}

// ---------------- per-graph avg / max pooling (graph_indicator sorted) ----------------
__device__ __forceinline__ int lowerb(const int* a, int n, int v)
{
    int lo = 0, hi = n;
    while (lo < hi) { int m = (lo + hi) >> 1; if (a[m] < v) lo = m + 1; else hi = m; }
    return lo;
}

__global__ __launch_bounds__(384) void pool_k(const float* __restrict__ g1,
                                              const float* __restrict__ g2,
                                              const float* __restrict__ g3,
                                              const float* __restrict__ score,
                                              const int* __restrict__ gi,
                                              float* __restrict__ pooled)
{
    int g = blockIdx.x;         // 0..63
    int c = threadIdx.x;        // 0..383
    __shared__ int sS, sE;
    if (c == 0) sS = lowerb(gi, N_NODES, g);
    if (c == 1) sE = lowerb(gi, N_NODES, g + 1);
    __syncthreads();
    int start = sS, end = sE;

    const float* base = (c < 128) ? g1 : (c < 256) ? g2 : g3;
    int cc = c & 127;

    float sum = 0.f, mx = -INFINITY;
    for (int n = start; n < end; ++n) {
        float v = base[(size_t)n * 128 + cc] * score[n];
        sum += v;
        mx = fmaxf(mx, v);
    }
    float cnt = (float)(end - start);
    pooled[g * 768 + c]       = sum / fmaxf(cnt, 1.f);
    pooled[g * 768 + 384 + c] = mx;
}

// ---------------- out = relu(pooled @ Wf + bf) : [64,768]@[768,128] ----------------
__global__ __launch_bounds__(128) void final_k(const float* __restrict__ pooled,
                                               const float* __restrict__ Wf,
                                               const float* __restrict__ bf,
                                               float* __restrict__ out)
{
    int g = blockIdx.x, c = threadIdx.x;
    __shared__ float pr[768];
    for (int i = c; i < 768; i += 128) pr[i] = pooled[g * 768 + i];
    __syncthreads();
    float acc = bf[c];
#pragma unroll 8
    for (int k = 0; k < 768; ++k) acc = fmaf(pr[k], Wf[k * 128 + c], acc);
    out[g * 128 + c] = fmaxf(acc, 0.f);
}

// ---------------- launch ----------------
extern "C" void kernel_launch(void* const* d_in, const int* in_sizes, int n_in,
                              void* d_out, int out_size)
{
    const int*   ei  = (const int*)d_in[0];   // [2, E] int32
    const float* ew  = (const float*)d_in[1];
    const float* X   = (const float*)d_in[2];
    const int*   gi  = (const int*)d_in[3];   // [N] int32 (sorted)
    const float* W1  = (const float*)d_in[4];
    const float* b1  = (const float*)d_in[5];
    const float* W2  = (const float*)d_in[6];
    const float* b2  = (const float*)d_in[7];
    const float* W3  = (const float*)d_in[8];
    const float* b3  = (const float*)d_in[9];
    const float* wa  = (const float*)d_in[10];
    const float* ba  = (const float*)d_in[11];
    const float* Wf  = (const float*)d_in[12];
    const float* bf  = (const float*)d_in[13];
    float* out = (float*)d_out;

    const int* src = ei;
    const int* dst = ei + N_EDGES;

    void *pS, *pG1, *pG2, *pG3, *pT, *pSC, *pPOOL;
    cudaGetSymbolAddress(&pS,   d_S);
    cudaGetSymbolAddress(&pG1,  d_G1);
    cudaGetSymbolAddress(&pG2,  d_G2);
    cudaGetSymbolAddress(&pG3,  d_G3);
    cudaGetSymbolAddress(&pT,   d_T);
    cudaGetSymbolAddress(&pSC,  d_SC);
    cudaGetSymbolAddress(&pPOOL, d_POOL);

    float* S  = (float*)pS;
    float* G1 = (float*)pG1;
    float* G2 = (float*)pG2;
    float* G3 = (float*)pG3;
    float* T  = (float*)pT;
    float* SC = (float*)pSC;
    float* PO = (float*)pPOOL;

    const int gemm_grid    = (N_NODES + 127) / 128;                 // 391
    const int scat_grid    = (N_EDGES * 32 + 255) / 256;            // 100000
    const int br_grid      = (N_NODES * 32 + 255) / 256;            // 6250
    const int att_grid     = (N_NODES * 32 + 255) / 256;
    const int scat1_grid   = (N_EDGES + 255) / 256;
    const int score_grid   = (N_NODES + 255) / 256;
    const size_t feat_bytes = (size_t)N_NODES * HID * sizeof(float);

    // layer 1
    gemm128<<<gemm_grid, 256>>>(X, W1, S, N_NODES);
    cudaMemsetAsync(G1, 0, feat_bytes);
    scatter128<<<scat_grid, 256>>>(src, dst, ew, S, G1);
    bias_relu<<<br_grid, 256>>>(G1, b1);

    // layer 2
    gemm128<<<gemm_grid, 256>>>(G1, W2, S, N_NODES);
    cudaMemsetAsync(G2, 0, feat_bytes);
    scatter128<<<scat_grid, 256>>>(src, dst, ew, S, G2);
    bias_relu<<<br_grid, 256>>>(G2, b2);

    // layer 3
    gemm128<<<gemm_grid, 256>>>(G2, W3, S, N_NODES);
    cudaMemsetAsync(G3, 0, feat_bytes);
    scatter128<<<scat_grid, 256>>>(src, dst, ew, S, G3);
    bias_relu<<<br_grid, 256>>>(G3, b3);

    // attention score: t = h @ wa ; sc[dst] += w_e * t[src] ; sc = tanh(sc + ba)
    att_t<<<att_grid, 256>>>(G1, G2, G3, wa, T);
    cudaMemsetAsync(SC, 0, N_NODES * sizeof(float));
    scatter_scalar<<<scat1_grid, 256>>>(src, dst, ew, T, SC);
    score_k<<<score_grid, 256>>>(SC, ba);

    // per-graph pooling + final FC
    pool_k<<<N_GRAPHS, 384>>>(G1, G2, G3, SC, gi, PO);
    final_k<<<N_GRAPHS, 128>>>(PO, Wf, bf, out);

    (void)in_sizes; (void)n_in; (void)out_size;
}

// round 4
// speedup vs baseline: 1.5724x; 1.5724x over previous
#include <cuda_runtime.h>
#include <cuda_bf16.h>
#include <math.h>

#define N_NODES 50000
#define N_EDGES 800000
#define HID     128
#define N_GRAPHS 64

// ---------------- scratch (allocation-free: __device__ globals) ----------------
__device__ float d_S [N_NODES * HID];   // GEMM output / gather source
__device__ float d_G1[N_NODES * HID];
__device__ float d_G2[N_NODES * HID];
__device__ float d_G3[N_NODES * HID];
__device__ float d_T [N_NODES];         // h @ wa per node
__device__ float d_SC[N_NODES];         // tanh attention score
__device__ float d_POOL[N_GRAPHS * 6 * HID];
// CSR scratch
__device__ int   d_CNT[N_NODES];
__device__ int   d_ROWPTR[N_NODES + 1];
__device__ int   d_CUR[N_NODES];
__device__ int   d_ESRC[N_EDGES];
__device__ float d_EWS [N_EDGES];
// pooling partials
__device__ float d_PPS[N_GRAPHS * 4 * 384];
__device__ float d_PPM[N_GRAPHS * 4 * 384];
__device__ int   d_GCNT[N_GRAPHS];

// ================= CSR build =================
__global__ __launch_bounds__(256) void csr_count(const int* __restrict__ dst, int* __restrict__ cnt)
{
    int e = blockIdx.x * blockDim.x + threadIdx.x;
    if (e < N_EDGES) atomicAdd(&cnt[dst[e]], 1);
}

// single-block exclusive scan of cnt[0..N_NODES) -> rowptr, rowptr[N]=E
__global__ __launch_bounds__(1024) void csr_scan(const int* __restrict__ cnt, int* __restrict__ rowptr)
{
    __shared__ int warpsum[32];
    __shared__ int carry;
    int t = threadIdx.x, lane = t & 31, w = t >> 5;
    if (t == 0) carry = 0;
    __syncthreads();
    for (int base = 0; base < N_NODES; base += 1024) {
        int i = base + t;
        int v = (i < N_NODES) ? cnt[i] : 0;
        // warp inclusive scan
        int x = v;
#pragma unroll
        for (int off = 1; off < 32; off <<= 1) {
            int y = __shfl_up_sync(0xFFFFFFFFu, x, off);
            if (lane >= off) x += y;
        }
        if (lane == 31) warpsum[w] = x;
        __syncthreads();
        if (w == 0) {
            int s = warpsum[lane];
#pragma unroll
            for (int off = 1; off < 32; off <<= 1) {
                int y = __shfl_up_sync(0xFFFFFFFFu, s, off);
                if (lane >= off) s += y;
            }
            warpsum[lane] = s;
        }
        __syncthreads();
        int incl = x + (w > 0 ? warpsum[w - 1] : 0);
        if (i < N_NODES) rowptr[i] = carry + incl - v;   // exclusive
        __syncthreads();
        if (t == 1023) carry += warpsum[31];
        __syncthreads();
    }
    if (t == 0) rowptr[N_NODES] = carry;
}

__global__ __launch_bounds__(256) void csr_fill(const int* __restrict__ src,
                                                const int* __restrict__ dst,
                                                const float* __restrict__ ew,
                                                int* __restrict__ cur,
                                                int* __restrict__ esrc,
                                                float* __restrict__ ews)
{
    int e = blockIdx.x * blockDim.x + threadIdx.x;
    if (e >= N_EDGES) return;
    int d = dst[e];
    int p = atomicAdd(&cur[d], 1);
    esrc[p] = src[e];
    ews[p]  = ew[e];
}

// ================= GEMM: out[nrows,128] = X[nrows,128] @ W[128,128] =================
__global__ __launch_bounds__(256, 2) void gemm128(const float* __restrict__ X,
                                                  const float* __restrict__ W,
                                                  float* __restrict__ out, int nrows)
{
    __shared__ float As[32 * 133];
    __shared__ float Bs[32 * 128];

    const int tid  = threadIdx.x;
    const int row0 = blockIdx.x * 128;
    const int tr   = tid >> 4;
    const int tc   = tid & 15;

    float acc[8][8];
#pragma unroll
    for (int i = 0; i < 8; ++i)
#pragma unroll
        for (int j = 0; j < 8; ++j) acc[i][j] = 0.f;

    for (int kc = 0; kc < 128; kc += 32) {
        __syncthreads();
#pragma unroll
        for (int it = 0; it < 16; ++it) {
            int idx = it * 256 + tid;
            int r   = idx >> 5;
            int kk  = idx & 31;
            int gr  = row0 + r;
            As[kk * 133 + r] = (gr < nrows) ? X[gr * 128 + kc + kk] : 0.f;
            Bs[idx] = W[kc * 128 + idx];
        }
        __syncthreads();
#pragma unroll
        for (int kk = 0; kk < 32; ++kk) {
            float a[8];
#pragma unroll
            for (int i = 0; i < 8; ++i) a[i] = As[kk * 133 + tr * 8 + i];
            float4 b0 = *(const float4*)&Bs[kk * 128 + tc * 8];
            float4 b1 = *(const float4*)&Bs[kk * 128 + tc * 8 + 4];
            float b[8] = {b0.x, b0.y, b0.z, b0.w, b1.x, b1.y, b1.z, b1.w};
#pragma unroll
            for (int i = 0; i < 8; ++i)
#pragma unroll
                for (int j = 0; j < 8; ++j) acc[i][j] = fmaf(a[i], b[j], acc[i][j]);
        }
    }

#pragma unroll
    for (int i = 0; i < 8; ++i) {
        int gr = row0 + tr * 8 + i;
        if (gr < nrows) {
            float4 v0 = make_float4(acc[i][0], acc[i][1], acc[i][2], acc[i][3]);
            float4 v1 = make_float4(acc[i][4], acc[i][5], acc[i][6], acc[i][7]);
            *(float4*)&out[gr * 128 + tc * 8]     = v0;
            *(float4*)&out[gr * 128 + tc * 8 + 4] = v1;
        }
    }
}

// ========== CSR gather: out[n] = relu( sum_e w_e * S[esrc[e]] + b ), warp/node ==========
__global__ __launch_bounds__(256) void gather_relu(const int* __restrict__ rowptr,
                                                   const int* __restrict__ esrc,
                                                   const float* __restrict__ ews,
                                                   const float* __restrict__ S,
                                                   const float* __restrict__ b,
                                                   float* __restrict__ out)
{
    int gt   = blockIdx.x * blockDim.x + threadIdx.x;
    int node = gt >> 5;
    int lane = gt & 31;
    if (node >= N_NODES) return;

    int e0 = rowptr[node], e1 = rowptr[node + 1];
    float4 acc = make_float4(0.f, 0.f, 0.f, 0.f);

    int e = e0;
    for (; e + 1 < e1; e += 2) {
        int   s0 = __ldg(esrc + e);
        int   s1 = __ldg(esrc + e + 1);
        float w0 = __ldg(ews + e);
        float w1 = __ldg(ews + e + 1);
        float4 v0 = ((const float4*)(S + (size_t)s0 * 128))[lane];
        float4 v1 = ((const float4*)(S + (size_t)s1 * 128))[lane];
        acc.x = fmaf(w0, v0.x, acc.x); acc.y = fmaf(w0, v0.y, acc.y);
        acc.z = fmaf(w0, v0.z, acc.z); acc.w = fmaf(w0, v0.w, acc.w);
        acc.x = fmaf(w1, v1.x, acc.x); acc.y = fmaf(w1, v1.y, acc.y);
        acc.z = fmaf(w1, v1.z, acc.z); acc.w = fmaf(w1, v1.w, acc.w);
    }
    if (e < e1) {
        int   s0 = __ldg(esrc + e);
        float w0 = __ldg(ews + e);
        float4 v0 = ((const float4*)(S + (size_t)s0 * 128))[lane];
        acc.x = fmaf(w0, v0.x, acc.x); acc.y = fmaf(w0, v0.y, acc.y);
        acc.z = fmaf(w0, v0.z, acc.z); acc.w = fmaf(w0, v0.w, acc.w);
    }

    float4 bb = ((const float4*)b)[lane];
    acc.x = fmaxf(acc.x + bb.x, 0.f);
    acc.y = fmaxf(acc.y + bb.y, 0.f);
    acc.z = fmaxf(acc.z + bb.z, 0.f);
    acc.w = fmaxf(acc.w + bb.w, 0.f);
    ((float4*)(out + (size_t)node * 128))[lane] = acc;
}

// ---------------- t[node] = h[node,:] @ wa  (h = [g1|g2|g3]), 1 warp/node ----------------
__global__ __launch_bounds__(256) void att_t(const float* __restrict__ g1,
                                             const float* __restrict__ g2,
                                             const float* __restrict__ g3,
                                             const float* __restrict__ wa,
                                             float* __restrict__ t)
{
    int gt   = blockIdx.x * blockDim.x + threadIdx.x;
    int node = gt >> 5;
    int lane = gt & 31;
    if (node >= N_NODES) return;

    float4 a1 = ((const float4*)(g1 + (size_t)node * 128))[lane];
    float4 a2 = ((const float4*)(g2 + (size_t)node * 128))[lane];
    float4 a3 = ((const float4*)(g3 + (size_t)node * 128))[lane];
    float4 w1 = ((const float4*)wa)[lane];
    float4 w2 = ((const float4*)wa)[32 + lane];
    float4 w3 = ((const float4*)wa)[64 + lane];

    float s = a1.x * w1.x + a1.y * w1.y + a1.z * w1.z + a1.w * w1.w
            + a2.x * w2.x + a2.y * w2.y + a2.z * w2.z + a2.w * w2.w
            + a3.x * w3.x + a3.y * w3.y + a3.z * w3.z + a3.w * w3.w;
#pragma unroll
    for (int off = 16; off; off >>= 1) s += __shfl_xor_sync(0xFFFFFFFFu, s, off);
    if (lane == 0) t[node] = s;
}

// ---------- sc[node] = tanh( sum_e w_e * t[esrc[e]] + ba ), warp/node ----------
__global__ __launch_bounds__(256) void gather_score(const int* __restrict__ rowptr,
                                                    const int* __restrict__ esrc,
                                                    const float* __restrict__ ews,
                                                    const float* __restrict__ t,
                                                    const float* __restrict__ ba,
                                                    float* __restrict__ sc)
{
    int gt   = blockIdx.x * blockDim.x + threadIdx.x;
    int node = gt >> 5;
    int lane = gt & 31;
    if (node >= N_NODES) return;

    int e0 = rowptr[node], e1 = rowptr[node + 1];
    float s = 0.f;
    for (int e = e0 + lane; e < e1; e += 32)
        s = fmaf(__ldg(ews + e), __ldg(t + __ldg(esrc + e)), s);
#pragma unroll
    for (int off = 16; off; off >>= 1) s += __shfl_xor_sync(0xFFFFFFFFu, s, off);
    if (lane == 0) sc[node] = tanhf(s + ba[0]);
}

// ---------------- per-graph pooling: 4 partial blocks per graph ----------------
__device__ __forceinline__ int lowerb(const int* a, int n, int v)
{
    int lo = 0, hi = n;
    while (lo < hi) { int m = (lo + hi) >> 1; if (a[m] < v) lo = m + 1; else hi = m; }
    return lo;
}

__global__ __launch_bounds__(384) void pool_part(const float* __restrict__ g1,
                                                 const float* __restrict__ g2,
                                                 const float* __restrict__ g3,
                                                 const float* __restrict__ score,
                                                 const int* __restrict__ gi,
                                                 float* __restrict__ pps,
                                                 float* __restrict__ ppm,
                                                 int* __restrict__ gcnt)
{
    int b = blockIdx.x;          // 0..255
    int g = b >> 2, part = b & 3;
    int c = threadIdx.x;         // 0..383
    __shared__ int sS, sE;
    if (c == 0) sS = lowerb(gi, N_NODES, g);
    if (c == 1) sE = lowerb(gi, N_NODES, g + 1);
    __syncthreads();
    int start = sS, end = sE, len = end - start;
    int n0 = start + (len * part) / 4;
    int n1 = start + (len * (part + 1)) / 4;

    const float* base = (c < 128) ? g1 : (c < 256) ? g2 : g3;
    int cc = c & 127;

    float sum = 0.f, mx = -INFINITY;
    for (int n = n0; n < n1; ++n) {
        float v = base[(size_t)n * 128 + cc] * score[n];
        sum += v;
        mx = fmaxf(mx, v);
    }
    pps[b * 384 + c] = sum;
    ppm[b * 384 + c] = mx;
    if (part == 0 && c == 0) gcnt[g] = len;
}

__global__ __launch_bounds__(384) void pool_comb(const float* __restrict__ pps,
                                                 const float* __restrict__ ppm,
                                                 const int* __restrict__ gcnt,
                                                 float* __restrict__ pooled)
{
    int g = blockIdx.x, c = threadIdx.x;
    float sum = 0.f, mx = -INFINITY;
#pragma unroll
    for (int p = 0; p < 4; ++p) {
        sum += pps[(g * 4 + p) * 384 + c];
        mx = fmaxf(mx, ppm[(g * 4 + p) * 384 + c]);
    }
    float cnt = (float)gcnt[g];
    pooled[g * 768 + c]       = sum / fmaxf(cnt, 1.f);
    pooled[g * 768 + 384 + c] = mx;
}

// ---------------- out = relu(pooled @ Wf + bf) : [64,768]@[768,128] ----------------
__global__ __launch_bounds__(128) void final_k(const float* __restrict__ pooled,
                                               const float* __restrict__ Wf,
                                               const float* __restrict__ bf,
                                               float* __restrict__ out)
{
    int g = blockIdx.x, c = threadIdx.x;
    __shared__ float pr[768];
    for (int i = c; i < 768; i += 128) pr[i] = pooled[g * 768 + i];
    __syncthreads();
    float acc = bf[c];
#pragma unroll 8
    for (int k = 0; k < 768; ++k) acc = fmaf(pr[k], Wf[k * 128 + c], acc);
    out[g * 128 + c] = fmaxf(acc, 0.f);
}

// ---------------- launch ----------------
extern "C" void kernel_launch(void* const* d_in, const int* in_sizes, int n_in,
                              void* d_out, int out_size)
{
    const int*   ei  = (const int*)d_in[0];   // [2, E] int32
    const float* ew  = (const float*)d_in[1];
    const float* X   = (const float*)d_in[2];
    const int*   gi  = (const int*)d_in[3];   // [N] int32 (sorted)
    const float* W1  = (const float*)d_in[4];
    const float* b1  = (const float*)d_in[5];
    const float* W2  = (const float*)d_in[6];
    const float* b2  = (const float*)d_in[7];
    const float* W3  = (const float*)d_in[8];
    const float* b3  = (const float*)d_in[9];
    const float* wa  = (const float*)d_in[10];
    const float* ba  = (const float*)d_in[11];
    const float* Wf  = (const float*)d_in[12];
    const float* bf  = (const float*)d_in[13];
    float* out = (float*)d_out;

    const int* src = ei;
    const int* dst = ei + N_EDGES;

    void *pS, *pG1, *pG2, *pG3, *pT, *pSC, *pPOOL;
    void *pCNT, *pRP, *pCUR, *pESRC, *pEWS, *pPPS, *pPPM, *pGC;
    cudaGetSymbolAddress(&pS,   d_S);
    cudaGetSymbolAddress(&pG1,  d_G1);
    cudaGetSymbolAddress(&pG2,  d_G2);
    cudaGetSymbolAddress(&pG3,  d_G3);
    cudaGetSymbolAddress(&pT,   d_T);
    cudaGetSymbolAddress(&pSC,  d_SC);
    cudaGetSymbolAddress(&pPOOL, d_POOL);
    cudaGetSymbolAddress(&pCNT, d_CNT);
    cudaGetSymbolAddress(&pRP,  d_ROWPTR);
    cudaGetSymbolAddress(&pCUR, d_CUR);
    cudaGetSymbolAddress(&pESRC, d_ESRC);
    cudaGetSymbolAddress(&pEWS,  d_EWS);
    cudaGetSymbolAddress(&pPPS, d_PPS);
    cudaGetSymbolAddress(&pPPM, d_PPM);
    cudaGetSymbolAddress(&pGC,  d_GCNT);

    float* S   = (float*)pS;
    float* G1  = (float*)pG1;
    float* G2  = (float*)pG2;
    float* G3  = (float*)pG3;
    float* T   = (float*)pT;
    float* SC  = (float*)pSC;
    float* PO  = (float*)pPOOL;
    int*   CNT = (int*)pCNT;
    int*   RP  = (int*)pRP;
    int*   CUR = (int*)pCUR;
    int*   ESRC = (int*)pESRC;
    float* EWS  = (float*)pEWS;
    float* PPS = (float*)pPPS;
    float* PPM = (float*)pPPM;
    int*   GC  = (int*)pGC;

    const int gemm_grid   = (N_NODES + 127) / 128;          // 391
    const int edge_grid   = (N_EDGES + 255) / 256;          // 3125
    const int warp_grid   = (N_NODES * 32 + 255) / 256;     // 6250

    // ---- CSR build (once per launch) ----
    cudaMemsetAsync(CNT, 0, N_NODES * sizeof(int));
    csr_count<<<edge_grid, 256>>>(dst, CNT);
    csr_scan<<<1, 1024>>>(CNT, RP);
    cudaMemcpyAsync(CUR, RP, N_NODES * sizeof(int), cudaMemcpyDeviceToDevice);
    csr_fill<<<edge_grid, 256>>>(src, dst, ew, CUR, ESRC, EWS);

    // ---- layer 1 ----
    gemm128<<<gemm_grid, 256>>>(X, W1, S, N_NODES);
    gather_relu<<<warp_grid, 256>>>(RP, ESRC, EWS, S, b1, G1);
    // ---- layer 2 ----
    gemm128<<<gemm_grid, 256>>>(G1, W2, S, N_NODES);
    gather_relu<<<warp_grid, 256>>>(RP, ESRC, EWS, S, b2, G2);
    // ---- layer 3 ----
    gemm128<<<gemm_grid, 256>>>(G2, W3, S, N_NODES);
    gather_relu<<<warp_grid, 256>>>(RP, ESRC, EWS, S, b3, G3);

    // ---- attention score ----
    att_t<<<warp_grid, 256>>>(G1, G2, G3, wa, T);
    gather_score<<<warp_grid, 256>>>(RP, ESRC, EWS, T, ba, SC);

    // ---- pooling + final FC ----
    pool_part<<<N_GRAPHS * 4, 384>>>(G1, G2, G3, SC, gi, PPS, PPM, GC);
    pool_comb<<<N_GRAPHS, 384>>>(PPS, PPM, GC, PO);
    final_k<<<N_GRAPHS, 128>>>(PO, Wf, bf, out);

    (void)in_sizes; (void)n_in; (void)out_size;
}

// round 6
// speedup vs baseline: 1.6091x; 1.0234x over previous
#include <cuda_runtime.h>
#include <cuda_bf16.h>
#include <math.h>

#define N_NODES 50000
#define N_EDGES 800000
#define HID     128
#define N_GRAPHS 64

typedef unsigned long long ull;

// ---------------- scratch (allocation-free: __device__ globals) ----------------
__device__ float d_S [N_NODES * HID];
__device__ float d_G1[N_NODES * HID];
__device__ float d_G2[N_NODES * HID];
__device__ float d_G3[N_NODES * HID];
__device__ float d_T [N_NODES];
__device__ float d_SC[N_NODES];
__device__ float d_POOL[N_GRAPHS * 6 * HID];
// CSR scratch
__device__ int   d_CNT[N_NODES];
__device__ int   d_ROWPTR[N_NODES + 1];
__device__ int   d_CUR[N_NODES];
__device__ int   d_ESRC[N_EDGES];
__device__ float d_EWS [N_EDGES];
// pooling partials
__device__ float d_PPS[N_GRAPHS * 4 * 384];
__device__ float d_PPM[N_GRAPHS * 4 * 384];
__device__ int   d_GCNT[N_GRAPHS];

// ---- packed fp32x2 helpers (sm_103a dual-FMA pipe) ----
__device__ __forceinline__ ull pack2(float lo, float hi)
{
    ull r;
    asm("mov.b64 %0, {%1, %2};" : "=l"(r) : "f"(lo), "f"(hi));
    return r;
}
#define FFMA2(d, a, b, c) asm("fma.rn.f32x2 %0, %1, %2, %3;" : "=l"(d) : "l"(a), "l"(b), "l"(c))

// ================= CSR build =================
__global__ __launch_bounds__(256) void csr_count(const int* __restrict__ dst, int* __restrict__ cnt)
{
    int e = blockIdx.x * blockDim.x + threadIdx.x;
    if (e < N_EDGES) atomicAdd(&cnt[dst[e]], 1);
}

__global__ __launch_bounds__(1024) void csr_scan(const int* __restrict__ cnt, int* __restrict__ rowptr)
{
    __shared__ int warpsum[32];
    __shared__ int carry;
    int t = threadIdx.x, lane = t & 31, w = t >> 5;
    if (t == 0) carry = 0;
    __syncthreads();
    for (int base = 0; base < N_NODES; base += 1024) {
        int i = base + t;
        int v = (i < N_NODES) ? cnt[i] : 0;
        int x = v;
#pragma unroll
        for (int off = 1; off < 32; off <<= 1) {
            int y = __shfl_up_sync(0xFFFFFFFFu, x, off);
            if (lane >= off) x += y;
        }
        if (lane == 31) warpsum[w] = x;
        __syncthreads();
        if (w == 0) {
            int s = warpsum[lane];
#pragma unroll
            for (int off = 1; off < 32; off <<= 1) {
                int y = __shfl_up_sync(0xFFFFFFFFu, s, off);
                if (lane >= off) s += y;
            }
            warpsum[lane] = s;
        }
        __syncthreads();
        int incl = x + (w > 0 ? warpsum[w - 1] : 0);
        if (i < N_NODES) rowptr[i] = carry + incl - v;
        __syncthreads();
        if (t == 1023) carry += warpsum[31];
        __syncthreads();
    }
    if (t == 0) rowptr[N_NODES] = carry;
}

__global__ __launch_bounds__(256) void csr_fill(const int* __restrict__ src,
                                                const int* __restrict__ dst,
                                                const float* __restrict__ ew,
                                                int* __restrict__ cur,
                                                int* __restrict__ esrc,
                                                float* __restrict__ ews)
{
    int e = blockIdx.x * blockDim.x + threadIdx.x;
    if (e >= N_EDGES) return;
    int d = dst[e];
    int p = atomicAdd(&cur[d], 1);
    esrc[p] = src[e];
    ews[p]  = ew[e];
}

// ============ GEMM: out[nrows,128] = X[nrows,128] @ W[128,128], f32x2 packed ============
__global__ __launch_bounds__(256, 2) void gemm128(const float* __restrict__ X,
                                                  const float* __restrict__ W,
                                                  float* __restrict__ out, int nrows)
{
    __shared__ float As[32 * 133];   // [kk][row] transposed, padded
    __shared__ float Bs[32 * 128];   // [kk][col]

    const int tid  = threadIdx.x;
    const int row0 = blockIdx.x * 128;
    const int tr   = tid >> 4;   // 0..15
    const int tc   = tid & 15;   // 0..15

    ull acc2[8][4];
#pragma unroll
    for (int i = 0; i < 8; ++i)
#pragma unroll
        for (int j = 0; j < 4; ++j) acc2[i][j] = 0ULL;   // packed {0.f,0.f}

    for (int kc = 0; kc < 128; kc += 32) {
        __syncthreads();
#pragma unroll
        for (int it = 0; it < 16; ++it) {
            int idx = it * 256 + tid;
            int r   = idx >> 5;
            int kk  = idx & 31;
            int gr  = row0 + r;
            As[kk * 133 + r] = (gr < nrows) ? X[gr * 128 + kc + kk] : 0.f;
            Bs[idx] = W[kc * 128 + idx];
        }
        __syncthreads();
#pragma unroll
        for (int kk = 0; kk < 32; ++kk) {
            ull a2[8];
#pragma unroll
            for (int i = 0; i < 8; ++i) {
                float av = As[kk * 133 + tr * 8 + i];
                a2[i] = pack2(av, av);
            }
            const ull* bp = (const ull*)&Bs[kk * 128 + tc * 8];
            ull b2[4];
#pragma unroll
            for (int j = 0; j < 4; ++j) b2[j] = bp[j];
#pragma unroll
            for (int i = 0; i < 8; ++i)
#pragma unroll
                for (int j = 0; j < 4; ++j)
                    FFMA2(acc2[i][j], a2[i], b2[j], acc2[i][j]);
        }
    }

#pragma unroll
    for (int i = 0; i < 8; ++i) {
        int gr = row0 + tr * 8 + i;
        if (gr < nrows) {
            ull* op = (ull*)&out[gr * 128 + tc * 8];
            // 2 x 128-bit stores
            ulonglong2 s0; s0.x = acc2[i][0]; s0.y = acc2[i][1];
            ulonglong2 s1; s1.x = acc2[i][2]; s1.y = acc2[i][3];
            ((ulonglong2*)op)[0] = s0;
            ((ulonglong2*)op)[1] = s1;
        }
    }
}

// ==== CSR gather + fused attention partial:
//  out[n] = relu( sum_e w_e * S[esrc[e]] + b );  T[n] (+)= out[n] . wa_seg
__global__ __launch_bounds__(256) void gather_relu(const int* __restrict__ rowptr,
                                                   const int* __restrict__ esrc,
                                                   const float* __restrict__ ews,
                                                   const float* __restrict__ S,
                                                   const float* __restrict__ b,
                                                   const float* __restrict__ wa_seg,
                                                   float* __restrict__ out,
                                                   float* __restrict__ T,
                                                   int accum)
{
    int gt   = blockIdx.x * blockDim.x + threadIdx.x;
    int node = gt >> 5;
    int lane = gt & 31;
    if (node >= N_NODES) return;

    int e0 = rowptr[node], e1 = rowptr[node + 1];
    float4 acc = make_float4(0.f, 0.f, 0.f, 0.f);

    int e = e0;
    for (; e + 1 < e1; e += 2) {
        int   s0 = __ldg(esrc + e);
        int   s1 = __ldg(esrc + e + 1);
        float w0 = __ldg(ews + e);
        float w1 = __ldg(ews + e + 1);
        float4 v0 = ((const float4*)(S + (size_t)s0 * 128))[lane];
        float4 v1 = ((const float4*)(S + (size_t)s1 * 128))[lane];
        acc.x = fmaf(w0, v0.x, acc.x); acc.y = fmaf(w0, v0.y, acc.y);
        acc.z = fmaf(w0, v0.z, acc.z); acc.w = fmaf(w0, v0.w, acc.w);
        acc.x = fmaf(w1, v1.x, acc.x); acc.y = fmaf(w1, v1.y, acc.y);
        acc.z = fmaf(w1, v1.z, acc.z); acc.w = fmaf(w1, v1.w, acc.w);
    }
    if (e < e1) {
        int   s0 = __ldg(esrc + e);
        float w0 = __ldg(ews + e);
        float4 v0 = ((const float4*)(S + (size_t)s0 * 128))[lane];
        acc.x = fmaf(w0, v0.x, acc.x); acc.y = fmaf(w0, v0.y, acc.y);
        acc.z = fmaf(w0, v0.z, acc.z); acc.w = fmaf(w0, v0.w, acc.w);
    }

    float4 bb = ((const float4*)b)[lane];
    acc.x = fmaxf(acc.x + bb.x, 0.f);
    acc.y = fmaxf(acc.y + bb.y, 0.f);
    acc.z = fmaxf(acc.z + bb.z, 0.f);
    acc.w = fmaxf(acc.w + bb.w, 0.f);
    ((float4*)(out + (size_t)node * 128))[lane] = acc;

    // fused attention partial: dot(relu_row, wa_seg)
    float4 ww = ((const float4*)wa_seg)[lane];
    float s = acc.x * ww.x + acc.y * ww.y + acc.z * ww.z + acc.w * ww.w;
#pragma unroll
    for (int off = 16; off; off >>= 1) s += __shfl_xor_sync(0xFFFFFFFFu, s, off);
    if (lane == 0) {
        if (accum) T[node] += s;
        else       T[node]  = s;
    }
}

// ---------- sc[node] = tanh( sum_e w_e * t[esrc[e]] + ba ), warp/node ----------
__global__ __launch_bounds__(256) void gather_score(const int* __restrict__ rowptr,
                                                    const int* __restrict__ esrc,
                                                    const float* __restrict__ ews,
                                                    const float* __restrict__ t,
                                                    const float* __restrict__ ba,
                                                    float* __restrict__ sc)
{
    int gt   = blockIdx.x * blockDim.x + threadIdx.x;
    int node = gt >> 5;
    int lane = gt & 31;
    if (node >= N_NODES) return;

    int e0 = rowptr[node], e1 = rowptr[node + 1];
    float s = 0.f;
    for (int e = e0 + lane; e < e1; e += 32)
        s = fmaf(__ldg(ews + e), __ldg(t + __ldg(esrc + e)), s);
#pragma unroll
    for (int off = 16; off; off >>= 1) s += __shfl_xor_sync(0xFFFFFFFFu, s, off);
    if (lane == 0) sc[node] = tanhf(s + ba[0]);
}

// ---------------- per-graph pooling: 4 partial blocks per graph ----------------
__device__ __forceinline__ int lowerb(const int* a, int n, int v)
{
    int lo = 0, hi = n;
    while (lo < hi) { int m = (lo + hi) >> 1; if (a[m] < v) lo = m + 1; else hi = m; }
    return lo;
}

__global__ __launch_bounds__(384) void pool_part(const float* __restrict__ g1,
                                                 const float* __restrict__ g2,
                                                 const float* __restrict__ g3,
                                                 const float* __restrict__ score,
                                                 const int* __restrict__ gi,
                                                 float* __restrict__ pps,
                                                 float* __restrict__ ppm,
                                                 int* __restrict__ gcnt)
{
    int b = blockIdx.x;
    int g = b >> 2, part = b & 3;
    int c = threadIdx.x;
    __shared__ int sS, sE;
    if (c == 0) sS = lowerb(gi, N_NODES, g);
    if (c == 1) sE = lowerb(gi, N_NODES, g + 1);
    __syncthreads();
    int start = sS, end = sE, len = end - start;
    int n0 = start + (len * part) / 4;
    int n1 = start + (len * (part + 1)) / 4;

    const float* base = (c < 128) ? g1 : (c < 256) ? g2 : g3;
    int cc = c & 127;

    float sum = 0.f, mx = -INFINITY;
    for (int n = n0; n < n1; ++n) {
        float v = base[(size_t)n * 128 + cc] * score[n];
        sum += v;
        mx = fmaxf(mx, v);
    }
    pps[b * 384 + c] = sum;
    ppm[b * 384 + c] = mx;
    if (part == 0 && c == 0) gcnt[g] = len;
}

__global__ __launch_bounds__(384) void pool_comb(const float* __restrict__ pps,
                                                 const float* __restrict__ ppm,
                                                 const int* __restrict__ gcnt,
                                                 float* __restrict__ pooled)
{
    int g = blockIdx.x, c = threadIdx.x;
    float sum = 0.f, mx = -INFINITY;
#pragma unroll
    for (int p = 0; p < 4; ++p) {
        sum += pps[(g * 4 + p) * 384 + c];
        mx = fmaxf(mx, ppm[(g * 4 + p) * 384 + c]);
    }
    float cnt = (float)gcnt[g];
    pooled[g * 768 + c]       = sum / fmaxf(cnt, 1.f);
    pooled[g * 768 + 384 + c] = mx;
}

// ---------------- out = relu(pooled @ Wf + bf) : [64,768]@[768,128] ----------------
__global__ __launch_bounds__(128) void final_k(const float* __restrict__ pooled,
                                               const float* __restrict__ Wf,
                                               const float* __restrict__ bf,
                                               float* __restrict__ out)
{
    int g = blockIdx.x, c = threadIdx.x;
    __shared__ float pr[768];
    for (int i = c; i < 768; i += 128) pr[i] = pooled[g * 768 + i];
    __syncthreads();
    float acc = bf[c];
#pragma unroll 8
    for (int k = 0; k < 768; ++k) acc = fmaf(pr[k], Wf[k * 128 + c], acc);
    out[g * 128 + c] = fmaxf(acc, 0.f);
}

// ---------------- launch ----------------
extern "C" void kernel_launch(void* const* d_in, const int* in_sizes, int n_in,
                              void* d_out, int out_size)
{
    const int*   ei  = (const int*)d_in[0];
    const float* ew  = (const float*)d_in[1];
    const float* X   = (const float*)d_in[2];
    const int*   gi  = (const int*)d_in[3];
    const float* W1  = (const float*)d_in[4];
    const float* b1  = (const float*)d_in[5];
    const float* W2  = (const float*)d_in[6];
    const float* b2  = (const float*)d_in[7];
    const float* W3  = (const float*)d_in[8];
    const float* b3  = (const float*)d_in[9];
    const float* wa  = (const float*)d_in[10];
    const float* ba  = (const float*)d_in[11];
    const float* Wf  = (const float*)d_in[12];
    const float* bf  = (const float*)d_in[13];
    float* out = (float*)d_out;

    const int* src = ei;
    const int* dst = ei + N_EDGES;

    void *pS, *pG1, *pG2, *pG3, *pT, *pSC, *pPOOL;
    void *pCNT, *pRP, *pCUR, *pESRC, *pEWS, *pPPS, *pPPM, *pGC;
    cudaGetSymbolAddress(&pS,   d_S);
    cudaGetSymbolAddress(&pG1,  d_G1);
    cudaGetSymbolAddress(&pG2,  d_G2);
    cudaGetSymbolAddress(&pG3,  d_G3);
    cudaGetSymbolAddress(&pT,   d_T);
    cudaGetSymbolAddress(&pSC,  d_SC);
    cudaGetSymbolAddress(&pPOOL, d_POOL);
    cudaGetSymbolAddress(&pCNT, d_CNT);
    cudaGetSymbolAddress(&pRP,  d_ROWPTR);
    cudaGetSymbolAddress(&pCUR, d_CUR);
    cudaGetSymbolAddress(&pESRC, d_ESRC);
    cudaGetSymbolAddress(&pEWS,  d_EWS);
    cudaGetSymbolAddress(&pPPS, d_PPS);
    cudaGetSymbolAddress(&pPPM, d_PPM);
    cudaGetSymbolAddress(&pGC,  d_GCNT);

    float* S   = (float*)pS;
    float* G1  = (float*)pG1;
    float* G2  = (float*)pG2;
    float* G3  = (float*)pG3;
    float* T   = (float*)pT;
    float* SC  = (float*)pSC;
    float* PO  = (float*)pPOOL;
    int*   CNT = (int*)pCNT;
    int*   RP  = (int*)pRP;
    int*   CUR = (int*)pCUR;
    int*   ESRC = (int*)pESRC;
    float* EWS  = (float*)pEWS;
    float* PPS = (float*)pPPS;
    float* PPM = (float*)pPPM;
    int*   GC  = (int*)pGC;

    const int gemm_grid = (N_NODES + 127) / 128;
    const int edge_grid = (N_EDGES + 255) / 256;
    const int warp_grid = (N_NODES * 32 + 255) / 256;

    // ---- CSR build ----
    cudaMemsetAsync(CNT, 0, N_NODES * sizeof(int));
    csr_count<<<edge_grid, 256>>>(dst, CNT);
    csr_scan<<<1, 1024>>>(CNT, RP);
    cudaMemcpyAsync(CUR, RP, N_NODES * sizeof(int), cudaMemcpyDeviceToDevice);
    csr_fill<<<edge_grid, 256>>>(src, dst, ew, CUR, ESRC, EWS);

    // ---- layer 1 ----
    gemm128<<<gemm_grid, 256>>>(X, W1, S, N_NODES);
    gather_relu<<<warp_grid, 256>>>(RP, ESRC, EWS, S, b1, wa,       G1, T, 0);
    // ---- layer 2 ----
    gemm128<<<gemm_grid, 256>>>(G1, W2, S, N_NODES);
    gather_relu<<<warp_grid, 256>>>(RP, ESRC, EWS, S, b2, wa + 128, G2, T, 1);
    // ---- layer 3 ----
    gemm128<<<gemm_grid, 256>>>(G2, W3, S, N_NODES);
    gather_relu<<<warp_grid, 256>>>(RP, ESRC, EWS, S, b3, wa + 256, G3, T, 1);

    // ---- attention score ----
    gather_score<<<warp_grid, 256>>>(RP, ESRC, EWS, T, ba, SC);

    // ---- pooling + final FC ----
    pool_part<<<N_GRAPHS * 4, 384>>>(G1, G2, G3, SC, gi, PPS, PPM, GC);
    pool_comb<<<N_GRAPHS, 384>>>(PPS, PPM, GC, PO);
    final_k<<<N_GRAPHS, 128>>>(PO, Wf, bf, out);

    (void)in_sizes; (void)n_in; (void)out_size;
}

// round 7
// speedup vs baseline: 1.8372x; 1.1418x over previous
#include <cuda_runtime.h>
#include <cuda_bf16.h>
#include <math.h>
#include <stdint.h>

#define N_NODES 50000
#define N_EDGES 800000
#define HID     128
#define N_GRAPHS 64

// ---------------- scratch (allocation-free: __device__ globals) ----------------
__device__ float d_S [N_NODES * HID];
__device__ float d_G1[N_NODES * HID];
__device__ float d_G2[N_NODES * HID];
__device__ float d_G3[N_NODES * HID];
__device__ float d_T [N_NODES];
__device__ float d_SC[N_NODES];
__device__ float d_POOL[N_GRAPHS * 6 * HID];
// CSR scratch
__device__ int   d_CNT[N_NODES];
__device__ int   d_ROWPTR[N_NODES + 1];
__device__ int   d_CUR[N_NODES];
__device__ int   d_ESRC[N_EDGES];
__device__ float d_EWS [N_EDGES];
// pooling partials
__device__ float d_PPS[N_GRAPHS * 4 * 384];
__device__ float d_PPM[N_GRAPHS * 4 * 384];
__device__ int   d_GCNT[N_GRAPHS];
// W converted: transposed [n][kpair] packed bf16x2, hi/lo, 3 layers
__device__ uint32_t d_WH[3][128 * 64];
__device__ uint32_t d_WL[3][128 * 64];

// ---- bf16 hi/lo split + pack ----
__device__ __forceinline__ void cvt_hilo(float x, float y, uint32_t& hi, uint32_t& lo)
{
    __nv_bfloat16 h0 = __float2bfloat16(x);
    __nv_bfloat16 h1 = __float2bfloat16(y);
    float rx = x - __bfloat162float(h0);
    float ry = y - __bfloat162float(h1);
    __nv_bfloat16 l0 = __float2bfloat16(rx);
    __nv_bfloat16 l1 = __float2bfloat16(ry);
    hi = ((uint32_t)__bfloat16_as_ushort(h1) << 16) | (uint32_t)__bfloat16_as_ushort(h0);
    lo = ((uint32_t)__bfloat16_as_ushort(l1) << 16) | (uint32_t)__bfloat16_as_ushort(l0);
}

#define MMA_BF16(c0,c1,c2,c3, a0,a1,a2,a3, b0,b1) \
    asm("mma.sync.aligned.m16n8k16.row.col.f32.bf16.bf16.f32 " \
        "{%0,%1,%2,%3}, {%4,%5,%6,%7}, {%8,%9}, {%0,%1,%2,%3};" \
        : "+f"(c0), "+f"(c1), "+f"(c2), "+f"(c3) \
        : "r"(a0), "r"(a1), "r"(a2), "r"(a3), "r"(b0), "r"(b1))

// ================= W prep: W[k][n] fp32 -> Wt[n][kpair] bf16x2 hi/lo =================
__global__ __launch_bounds__(256) void wprep(const float* __restrict__ W,
                                             uint32_t* __restrict__ hi,
                                             uint32_t* __restrict__ lo)
{
    int idx = blockIdx.x * blockDim.x + threadIdx.x;   // 0..8191
    if (idx >= 128 * 64) return;
    int n = idx >> 6, p = idx & 63;
    float w0 = W[(2 * p) * 128 + n];
    float w1 = W[(2 * p + 1) * 128 + n];
    uint32_t h, l;
    cvt_hilo(w0, w1, h, l);
    hi[n * 64 + p] = h;
    lo[n * 64 + p] = l;
}

// ================= CSR build =================
__global__ __launch_bounds__(256) void csr_count(const int* __restrict__ dst, int* __restrict__ cnt)
{
    int e = blockIdx.x * blockDim.x + threadIdx.x;
    if (e < N_EDGES) atomicAdd(&cnt[dst[e]], 1);
}

__global__ __launch_bounds__(1024) void csr_scan(const int* __restrict__ cnt, int* __restrict__ rowptr)
{
    __shared__ int warpsum[32];
    __shared__ int carry;
    int t = threadIdx.x, lane = t & 31, w = t >> 5;
    if (t == 0) carry = 0;
    __syncthreads();
    for (int base = 0; base < N_NODES; base += 1024) {
        int i = base + t;
        int v = (i < N_NODES) ? cnt[i] : 0;
        int x = v;
#pragma unroll
        for (int off = 1; off < 32; off <<= 1) {
            int y = __shfl_up_sync(0xFFFFFFFFu, x, off);
            if (lane >= off) x += y;
        }
        if (lane == 31) warpsum[w] = x;
        __syncthreads();
        if (w == 0) {
            int s = warpsum[lane];
#pragma unroll
            for (int off = 1; off < 32; off <<= 1) {
                int y = __shfl_up_sync(0xFFFFFFFFu, s, off);
                if (lane >= off) s += y;
            }
            warpsum[lane] = s;
        }
        __syncthreads();
        int incl = x + (w > 0 ? warpsum[w - 1] : 0);
        if (i < N_NODES) rowptr[i] = carry + incl - v;
        __syncthreads();
        if (t == 1023) carry += warpsum[31];
        __syncthreads();
    }
    if (t == 0) rowptr[N_NODES] = carry;
}

__global__ __launch_bounds__(256) void csr_fill(const int* __restrict__ src,
                                                const int* __restrict__ dst,
                                                const float* __restrict__ ew,
                                                int* __restrict__ cur,
                                                int* __restrict__ esrc,
                                                float* __restrict__ ews)
{
    int e = blockIdx.x * blockDim.x + threadIdx.x;
    if (e >= N_EDGES) return;
    int d = dst[e];
    int p = atomicAdd(&cur[d], 1);
    esrc[p] = src[e];
    ews[p]  = ew[e];
}

// ===== GEMM via bf16x3 tensor cores: out[nrows,128] = X[nrows,128] @ W[128,128] =====
// Block: 128 rows x 128 cols, 256 thr (8 warps as 4m x 2n; warp tile 32x64).
// K processed in 2 chunks of 64 (32 bf16x2 pairs), smem padded stride 36 (banks 4g+tig).
#define ASTR 36
#define SM_CH (128 * ASTR)          // u32 per buffer
#define GEMM_SMEM (4 * SM_CH * 4)   // bytes = 73728

__global__ __launch_bounds__(256, 2) void gemm_bf16x3(const float* __restrict__ X,
                                                      const uint32_t* __restrict__ Wthi,
                                                      const uint32_t* __restrict__ Wtlo,
                                                      float* __restrict__ out, int nrows)
{
    extern __shared__ uint32_t sm[];
    uint32_t* Ahi = sm;
    uint32_t* Alo = sm + SM_CH;
    uint32_t* Bhi = sm + 2 * SM_CH;
    uint32_t* Blo = sm + 3 * SM_CH;

    const int tid  = threadIdx.x;
    const int row0 = blockIdx.x * 128;
    const int warp = tid >> 5, lane = tid & 31;
    const int g    = lane >> 2, tig = lane & 3;
    const int wm   = warp >> 1, wn = warp & 1;

    float c[2][8][4];
#pragma unroll
    for (int mi = 0; mi < 2; ++mi)
#pragma unroll
        for (int ni = 0; ni < 8; ++ni)
#pragma unroll
            for (int q = 0; q < 4; ++q) c[mi][ni][q] = 0.f;

    for (int chunk = 0; chunk < 2; ++chunk) {
        int kp0 = chunk * 32;   // global pair offset
        __syncthreads();
#pragma unroll
        for (int i = 0; i < 16; ++i) {
            int idx = i * 256 + tid;       // 0..4095
            int r = idx >> 5, p = idx & 31;
            int gr = row0 + r;
            float2 v = (gr < nrows) ? *(const float2*)&X[(size_t)gr * 128 + (kp0 + p) * 2]
                                    : make_float2(0.f, 0.f);
            uint32_t h, l;
            cvt_hilo(v.x, v.y, h, l);
            Ahi[r * ASTR + p] = h;
            Alo[r * ASTR + p] = l;
            Bhi[r * ASTR + p] = Wthi[r * 64 + kp0 + p];
            Blo[r * ASTR + p] = Wtlo[r * 64 + kp0 + p];
        }
        __syncthreads();

        const int aB0 = (wm * 32 + g) * ASTR + tig;       // mi=0 base
        const int bB0 = (wn * 64 + g) * ASTR + tig;
#pragma unroll
        for (int ks = 0; ks < 4; ++ks) {
            int pb = ks * 8;
            uint32_t ah[2][4], al[2][4];
#pragma unroll
            for (int mi = 0; mi < 2; ++mi) {
                int ab = aB0 + mi * 16 * ASTR + pb;
                ah[mi][0] = Ahi[ab];
                ah[mi][1] = Ahi[ab + 8 * ASTR];
                ah[mi][2] = Ahi[ab + 4];
                ah[mi][3] = Ahi[ab + 8 * ASTR + 4];
                al[mi][0] = Alo[ab];
                al[mi][1] = Alo[ab + 8 * ASTR];
                al[mi][2] = Alo[ab + 4];
                al[mi][3] = Alo[ab + 8 * ASTR + 4];
            }
#pragma unroll
            for (int ni = 0; ni < 8; ++ni) {
                int bb = bB0 + ni * 8 * ASTR + pb;
                uint32_t bh0 = Bhi[bb];
                uint32_t bh1 = Bhi[bb + 4];
                uint32_t bl0 = Blo[bb];
                uint32_t bl1 = Blo[bb + 4];
#pragma unroll
                for (int mi = 0; mi < 2; ++mi) {
                    MMA_BF16(c[mi][ni][0], c[mi][ni][1], c[mi][ni][2], c[mi][ni][3],
                             ah[mi][0], ah[mi][1], ah[mi][2], ah[mi][3], bh0, bh1);
                    MMA_BF16(c[mi][ni][0], c[mi][ni][1], c[mi][ni][2], c[mi][ni][3],
                             ah[mi][0], ah[mi][1], ah[mi][2], ah[mi][3], bl0, bl1);
                    MMA_BF16(c[mi][ni][0], c[mi][ni][1], c[mi][ni][2], c[mi][ni][3],
                             al[mi][0], al[mi][1], al[mi][2], al[mi][3], bh0, bh1);
                }
            }
        }
    }

    // store: c0,c1 -> (row, 2tig..2tig+1), c2,c3 -> (row+8, same)
#pragma unroll
    for (int mi = 0; mi < 2; ++mi) {
        int r = row0 + wm * 32 + mi * 16 + g;
#pragma unroll
        for (int ni = 0; ni < 8; ++ni) {
            int cn = wn * 64 + ni * 8 + 2 * tig;
            if (r < nrows)
                *(float2*)&out[(size_t)r * 128 + cn] = make_float2(c[mi][ni][0], c[mi][ni][1]);
            if (r + 8 < nrows)
                *(float2*)&out[(size_t)(r + 8) * 128 + cn] = make_float2(c[mi][ni][2], c[mi][ni][3]);
        }
    }
}

// ==== CSR gather + fused attention partial ====
__global__ __launch_bounds__(256) void gather_relu(const int* __restrict__ rowptr,
                                                   const int* __restrict__ esrc,
                                                   const float* __restrict__ ews,
                                                   const float* __restrict__ S,
                                                   const float* __restrict__ b,
                                                   const float* __restrict__ wa_seg,
                                                   float* __restrict__ out,
                                                   float* __restrict__ T,
                                                   int accum)
{
    int gt   = blockIdx.x * blockDim.x + threadIdx.x;
    int node = gt >> 5;
    int lane = gt & 31;
    if (node >= N_NODES) return;

    int e0 = rowptr[node], e1 = rowptr[node + 1];
    float4 acc = make_float4(0.f, 0.f, 0.f, 0.f);

    int e = e0;
    for (; e + 3 < e1; e += 4) {
        int   s0 = __ldg(esrc + e),     s1 = __ldg(esrc + e + 1);
        int   s2 = __ldg(esrc + e + 2), s3 = __ldg(esrc + e + 3);
        float w0 = __ldg(ews + e),      w1 = __ldg(ews + e + 1);
        float w2 = __ldg(ews + e + 2),  w3 = __ldg(ews + e + 3);
        float4 v0 = ((const float4*)(S + (size_t)s0 * 128))[lane];
        float4 v1 = ((const float4*)(S + (size_t)s1 * 128))[lane];
        float4 v2 = ((const float4*)(S + (size_t)s2 * 128))[lane];
        float4 v3 = ((const float4*)(S + (size_t)s3 * 128))[lane];
        acc.x = fmaf(w0, v0.x, acc.x); acc.y = fmaf(w0, v0.y, acc.y);
        acc.z = fmaf(w0, v0.z, acc.z); acc.w = fmaf(w0, v0.w, acc.w);
        acc.x = fmaf(w1, v1.x, acc.x); acc.y = fmaf(w1, v1.y, acc.y);
        acc.z = fmaf(w1, v1.z, acc.z); acc.w = fmaf(w1, v1.w, acc.w);
        acc.x = fmaf(w2, v2.x, acc.x); acc.y = fmaf(w2, v2.y, acc.y);
        acc.z = fmaf(w2, v2.z, acc.z); acc.w = fmaf(w2, v2.w, acc.w);
        acc.x = fmaf(w3, v3.x, acc.x); acc.y = fmaf(w3, v3.y, acc.y);
        acc.z = fmaf(w3, v3.z, acc.z); acc.w = fmaf(w3, v3.w, acc.w);
    }
    for (; e < e1; ++e) {
        int   s0 = __ldg(esrc + e);
        float w0 = __ldg(ews + e);
        float4 v0 = ((const float4*)(S + (size_t)s0 * 128))[lane];
        acc.x = fmaf(w0, v0.x, acc.x); acc.y = fmaf(w0, v0.y, acc.y);
        acc.z = fmaf(w0, v0.z, acc.z); acc.w = fmaf(w0, v0.w, acc.w);
    }

    float4 bb = ((const float4*)b)[lane];
    acc.x = fmaxf(acc.x + bb.x, 0.f);
    acc.y = fmaxf(acc.y + bb.y, 0.f);
    acc.z = fmaxf(acc.z + bb.z, 0.f);
    acc.w = fmaxf(acc.w + bb.w, 0.f);
    ((float4*)(out + (size_t)node * 128))[lane] = acc;

    float4 ww = ((const float4*)wa_seg)[lane];
    float s = acc.x * ww.x + acc.y * ww.y + acc.z * ww.z + acc.w * ww.w;
#pragma unroll
    for (int off = 16; off; off >>= 1) s += __shfl_xor_sync(0xFFFFFFFFu, s, off);
    if (lane == 0) {
        if (accum) T[node] += s;
        else       T[node]  = s;
    }
}

// ---------- sc[node] = tanh( sum_e w_e * t[esrc[e]] + ba ), warp/node ----------
__global__ __launch_bounds__(256) void gather_score(const int* __restrict__ rowptr,
                                                    const int* __restrict__ esrc,
                                                    const float* __restrict__ ews,
                                                    const float* __restrict__ t,
                                                    const float* __restrict__ ba,
                                                    float* __restrict__ sc)
{
    int gt   = blockIdx.x * blockDim.x + threadIdx.x;
    int node = gt >> 5;
    int lane = gt & 31;
    if (node >= N_NODES) return;

    int e0 = rowptr[node], e1 = rowptr[node + 1];
    float s = 0.f;
    for (int e = e0 + lane; e < e1; e += 32)
        s = fmaf(__ldg(ews + e), __ldg(t + __ldg(esrc + e)), s);
#pragma unroll
    for (int off = 16; off; off >>= 1) s += __shfl_xor_sync(0xFFFFFFFFu, s, off);
    if (lane == 0) sc[node] = tanhf(s + ba[0]);
}

// ---------------- per-graph pooling ----------------
__device__ __forceinline__ int lowerb(const int* a, int n, int v)
{
    int lo = 0, hi = n;
    while (lo < hi) { int m = (lo + hi) >> 1; if (a[m] < v) lo = m + 1; else hi = m; }
    return lo;
}

__global__ __launch_bounds__(384) void pool_part(const float* __restrict__ g1,
                                                 const float* __restrict__ g2,
                                                 const float* __restrict__ g3,
                                                 const float* __restrict__ score,
                                                 const int* __restrict__ gi,
                                                 float* __restrict__ pps,
                                                 float* __restrict__ ppm,
                                                 int* __restrict__ gcnt)
{
    int b = blockIdx.x;
    int g = b >> 2, part = b & 3;
    int c = threadIdx.x;
    __shared__ int sS, sE;
    if (c == 0) sS = lowerb(gi, N_NODES, g);
    if (c == 1) sE = lowerb(gi, N_NODES, g + 1);
    __syncthreads();
    int start = sS, end = sE, len = end - start;
    int n0 = start + (len * part) / 4;
    int n1 = start + (len * (part + 1)) / 4;

    const float* base = (c < 128) ? g1 : (c < 256) ? g2 : g3;
    int cc = c & 127;

    float sum = 0.f, mx = -INFINITY;
    for (int n = n0; n < n1; ++n) {
        float v = base[(size_t)n * 128 + cc] * score[n];
        sum += v;
        mx = fmaxf(mx, v);
    }
    pps[b * 384 + c] = sum;
    ppm[b * 384 + c] = mx;
    if (part == 0 && c == 0) gcnt[g] = len;
}

__global__ __launch_bounds__(384) void pool_comb(const float* __restrict__ pps,
                                                 const float* __restrict__ ppm,
                                                 const int* __restrict__ gcnt,
                                                 float* __restrict__ pooled)
{
    int g = blockIdx.x, c = threadIdx.x;
    float sum = 0.f, mx = -INFINITY;
#pragma unroll
    for (int p = 0; p < 4; ++p) {
        sum += pps[(g * 4 + p) * 384 + c];
        mx = fmaxf(mx, ppm[(g * 4 + p) * 384 + c]);
    }
    float cnt = (float)gcnt[g];
    pooled[g * 768 + c]       = sum / fmaxf(cnt, 1.f);
    pooled[g * 768 + 384 + c] = mx;
}

// ---------------- out = relu(pooled @ Wf + bf) ----------------
__global__ __launch_bounds__(128) void final_k(const float* __restrict__ pooled,
                                               const float* __restrict__ Wf,
                                               const float* __restrict__ bf,
                                               float* __restrict__ out)
{
    int g = blockIdx.x, c = threadIdx.x;
    __shared__ float pr[768];
    for (int i = c; i < 768; i += 128) pr[i] = pooled[g * 768 + i];
    __syncthreads();
    float acc = bf[c];
#pragma unroll 8
    for (int k = 0; k < 768; ++k) acc = fmaf(pr[k], Wf[k * 128 + c], acc);
    out[g * 128 + c] = fmaxf(acc, 0.f);
}

// ---------------- launch ----------------
extern "C" void kernel_launch(void* const* d_in, const int* in_sizes, int n_in,
                              void* d_out, int out_size)
{
    const int*   ei  = (const int*)d_in[0];
    const float* ew  = (const float*)d_in[1];
    const float* X   = (const float*)d_in[2];
    const int*   gi  = (const int*)d_in[3];
    const float* W1  = (const float*)d_in[4];
    const float* b1  = (const float*)d_in[5];
    const float* W2  = (const float*)d_in[6];
    const float* b2  = (const float*)d_in[7];
    const float* W3  = (const float*)d_in[8];
    const float* b3  = (const float*)d_in[9];
    const float* wa  = (const float*)d_in[10];
    const float* ba  = (const float*)d_in[11];
    const float* Wf  = (const float*)d_in[12];
    const float* bf  = (const float*)d_in[13];
    float* out = (float*)d_out;

    const int* src = ei;
    const int* dst = ei + N_EDGES;

    static int smem_set = 0;
    if (!smem_set) {
        cudaFuncSetAttribute(gemm_bf16x3, cudaFuncAttributeMaxDynamicSharedMemorySize, GEMM_SMEM);
        smem_set = 1;
    }

    void *pS, *pG1, *pG2, *pG3, *pT, *pSC, *pPOOL;
    void *pCNT, *pRP, *pCUR, *pESRC, *pEWS, *pPPS, *pPPM, *pGC, *pWH, *pWL;
    cudaGetSymbolAddress(&pS,   d_S);
    cudaGetSymbolAddress(&pG1,  d_G1);
    cudaGetSymbolAddress(&pG2,  d_G2);
    cudaGetSymbolAddress(&pG3,  d_G3);
    cudaGetSymbolAddress(&pT,   d_T);
    cudaGetSymbolAddress(&pSC,  d_SC);
    cudaGetSymbolAddress(&pPOOL, d_POOL);
    cudaGetSymbolAddress(&pCNT, d_CNT);
    cudaGetSymbolAddress(&pRP,  d_ROWPTR);
    cudaGetSymbolAddress(&pCUR, d_CUR);
    cudaGetSymbolAddress(&pESRC, d_ESRC);
    cudaGetSymbolAddress(&pEWS,  d_EWS);
    cudaGetSymbolAddress(&pPPS, d_PPS);
    cudaGetSymbolAddress(&pPPM, d_PPM);
    cudaGetSymbolAddress(&pGC,  d_GCNT);
    cudaGetSymbolAddress(&pWH,  d_WH);
    cudaGetSymbolAddress(&pWL,  d_WL);

    float* S   = (float*)pS;
    float* G1  = (float*)pG1;
    float* G2  = (float*)pG2;
    float* G3  = (float*)pG3;
    float* T   = (float*)pT;
    float* SC  = (float*)pSC;
    float* PO  = (float*)pPOOL;
    int*   CNT = (int*)pCNT;
    int*   RP  = (int*)pRP;
    int*   CUR = (int*)pCUR;
    int*   ESRC = (int*)pESRC;
    float* EWS  = (float*)pEWS;
    float* PPS = (float*)pPPS;
    float* PPM = (float*)pPPM;
    int*   GC  = (int*)pGC;
    uint32_t* WH = (uint32_t*)pWH;   // [3][8192]
    uint32_t* WL = (uint32_t*)pWL;

    const int gemm_grid = (N_NODES + 127) / 128;
    const int edge_grid = (N_EDGES + 255) / 256;
    const int warp_grid = (N_NODES * 32 + 255) / 256;

    // ---- W conversion + CSR build ----
    wprep<<<32, 256>>>(W1, WH,          WL);
    wprep<<<32, 256>>>(W2, WH + 8192,   WL + 8192);
    wprep<<<32, 256>>>(W3, WH + 16384,  WL + 16384);
    cudaMemsetAsync(CNT, 0, N_NODES * sizeof(int));
    csr_count<<<edge_grid, 256>>>(dst, CNT);
    csr_scan<<<1, 1024>>>(CNT, RP);
    cudaMemcpyAsync(CUR, RP, N_NODES * sizeof(int), cudaMemcpyDeviceToDevice);
    csr_fill<<<edge_grid, 256>>>(src, dst, ew, CUR, ESRC, EWS);

    // ---- layer 1 ----
    gemm_bf16x3<<<gemm_grid, 256, GEMM_SMEM>>>(X, WH, WL, S, N_NODES);
    gather_relu<<<warp_grid, 256>>>(RP, ESRC, EWS, S, b1, wa,       G1, T, 0);
    // ---- layer 2 ----
    gemm_bf16x3<<<gemm_grid, 256, GEMM_SMEM>>>(G1, WH + 8192, WL + 8192, S, N_NODES);
    gather_relu<<<warp_grid, 256>>>(RP, ESRC, EWS, S, b2, wa + 128, G2, T, 1);
    // ---- layer 3 ----
    gemm_bf16x3<<<gemm_grid, 256, GEMM_SMEM>>>(G2, WH + 16384, WL + 16384, S, N_NODES);
    gather_relu<<<warp_grid, 256>>>(RP, ESRC, EWS, S, b3, wa + 256, G3, T, 1);

    // ---- attention score ----
    gather_score<<<warp_grid, 256>>>(RP, ESRC, EWS, T, ba, SC);

    // ---- pooling + final FC ----
    pool_part<<<N_GRAPHS * 4, 384>>>(G1, G2, G3, SC, gi, PPS, PPM, GC);
    pool_comb<<<N_GRAPHS, 384>>>(PPS, PPM, GC, PO);
    final_k<<<N_GRAPHS, 128>>>(PO, Wf, bf, out);

    (void)in_sizes; (void)n_in; (void)out_size;
}

// round 8
// speedup vs baseline: 2.0077x; 1.0928x over previous
#include <cuda_runtime.h>
#include <cuda_bf16.h>
#include <math.h>
#include <stdint.h>

#define N_NODES 50000
#define N_EDGES 800000
#define HID     128
#define N_GRAPHS 64

// ---------------- scratch (allocation-free: __device__ globals) ----------------
__device__ float d_S [N_NODES * HID];
__device__ float d_G1[N_NODES * HID];
__device__ float d_G2[N_NODES * HID];
__device__ float d_G3[N_NODES * HID];
__device__ float d_T [N_NODES];
__device__ float d_SC[N_NODES];
__device__ float d_POOL[N_GRAPHS * 6 * HID];
// CSR scratch
__device__ int   d_CNT[N_NODES];
__device__ int   d_ROWPTR[N_NODES + 1];
__device__ int   d_CUR[N_NODES];
__device__ int   d_ESRC[N_EDGES];
__device__ float d_EWS [N_EDGES];
// pooling partials
__device__ float d_PPS[N_GRAPHS * 4 * 384];
__device__ float d_PPM[N_GRAPHS * 4 * 384];
__device__ int   d_GCNT[N_GRAPHS];
// W converted: transposed [n][kpair] packed bf16x2, hi/lo, 3 layers
__device__ uint32_t d_WH[3][128 * 64];
__device__ uint32_t d_WL[3][128 * 64];

// ---- bf16 hi/lo split + pack ----
__device__ __forceinline__ void cvt_hilo(float x, float y, uint32_t& hi, uint32_t& lo)
{
    __nv_bfloat16 h0 = __float2bfloat16(x);
    __nv_bfloat16 h1 = __float2bfloat16(y);
    float rx = x - __bfloat162float(h0);
    float ry = y - __bfloat162float(h1);
    __nv_bfloat16 l0 = __float2bfloat16(rx);
    __nv_bfloat16 l1 = __float2bfloat16(ry);
    hi = ((uint32_t)__bfloat16_as_ushort(h1) << 16) | (uint32_t)__bfloat16_as_ushort(h0);
    lo = ((uint32_t)__bfloat16_as_ushort(l1) << 16) | (uint32_t)__bfloat16_as_ushort(l0);
}

#define MMA_BF16(c0,c1,c2,c3, a0,a1,a2,a3, b0,b1) \
    asm("mma.sync.aligned.m16n8k16.row.col.f32.bf16.bf16.f32 " \
        "{%0,%1,%2,%3}, {%4,%5,%6,%7}, {%8,%9}, {%0,%1,%2,%3};" \
        : "+f"(c0), "+f"(c1), "+f"(c2), "+f"(c3) \
        : "r"(a0), "r"(a1), "r"(a2), "r"(a3), "r"(b0), "r"(b1))

// ================= W prep: W[k][n] fp32 -> Wt[n][kpair] bf16x2 hi/lo =================
__global__ __launch_bounds__(256) void wprep(const float* __restrict__ W,
                                             uint32_t* __restrict__ hi,
                                             uint32_t* __restrict__ lo)
{
    int idx = blockIdx.x * blockDim.x + threadIdx.x;   // 0..8191
    if (idx >= 128 * 64) return;
    int n = idx >> 6, p = idx & 63;
    float w0 = W[(2 * p) * 128 + n];
    float w1 = W[(2 * p + 1) * 128 + n];
    uint32_t h, l;
    cvt_hilo(w0, w1, h, l);
    hi[n * 64 + p] = h;
    lo[n * 64 + p] = l;
}

// ================= CSR build =================
__global__ __launch_bounds__(256) void csr_count(const int* __restrict__ dst, int* __restrict__ cnt)
{
    int e = blockIdx.x * blockDim.x + threadIdx.x;
    if (e < N_EDGES) atomicAdd(&cnt[dst[e]], 1);
}

// single-block exclusive scan of cnt -> rowptr AND cur
__global__ __launch_bounds__(1024) void csr_scan(const int* __restrict__ cnt,
                                                 int* __restrict__ rowptr,
                                                 int* __restrict__ cur)
{
    __shared__ int warpsum[32];
    __shared__ int carry;
    int t = threadIdx.x, lane = t & 31, w = t >> 5;
    if (t == 0) carry = 0;
    __syncthreads();
    for (int base = 0; base < N_NODES; base += 1024) {
        int i = base + t;
        int v = (i < N_NODES) ? cnt[i] : 0;
        int x = v;
#pragma unroll
        for (int off = 1; off < 32; off <<= 1) {
            int y = __shfl_up_sync(0xFFFFFFFFu, x, off);
            if (lane >= off) x += y;
        }
        if (lane == 31) warpsum[w] = x;
        __syncthreads();
        if (w == 0) {
            int s = warpsum[lane];
#pragma unroll
            for (int off = 1; off < 32; off <<= 1) {
                int y = __shfl_up_sync(0xFFFFFFFFu, s, off);
                if (lane >= off) s += y;
            }
            warpsum[lane] = s;
        }
        __syncthreads();
        int incl = x + (w > 0 ? warpsum[w - 1] : 0);
        if (i < N_NODES) {
            int ex = carry + incl - v;
            rowptr[i] = ex;
            cur[i]    = ex;
        }
        __syncthreads();
        if (t == 1023) carry += warpsum[31];
        __syncthreads();
    }
    if (t == 0) rowptr[N_NODES] = carry;
}

__global__ __launch_bounds__(256) void csr_fill(const int* __restrict__ src,
                                                const int* __restrict__ dst,
                                                const float* __restrict__ ew,
                                                int* __restrict__ cur,
                                                int* __restrict__ esrc,
                                                float* __restrict__ ews)
{
    int e = blockIdx.x * blockDim.x + threadIdx.x;
    if (e >= N_EDGES) return;
    int d = dst[e];
    int p = atomicAdd(&cur[d], 1);
    esrc[p] = src[e];
    ews[p]  = ew[e];
}

// ===== GEMM via bf16x3 tensor cores: out[nrows,128] = X[nrows,128] @ W[128,128] =====
#define ASTR 36
#define SM_CH (128 * ASTR)
#define GEMM_SMEM (4 * SM_CH * 4)

__global__ __launch_bounds__(256, 2) void gemm_bf16x3(const float* __restrict__ X,
                                                      const uint32_t* __restrict__ Wthi,
                                                      const uint32_t* __restrict__ Wtlo,
                                                      float* __restrict__ out, int nrows)
{
    extern __shared__ uint32_t sm[];
    uint32_t* Ahi = sm;
    uint32_t* Alo = sm + SM_CH;
    uint32_t* Bhi = sm + 2 * SM_CH;
    uint32_t* Blo = sm + 3 * SM_CH;

    const int tid  = threadIdx.x;
    const int row0 = blockIdx.x * 128;
    const int warp = tid >> 5, lane = tid & 31;
    const int g    = lane >> 2, tig = lane & 3;
    const int wm   = warp >> 1, wn = warp & 1;

    float c[2][8][4];
#pragma unroll
    for (int mi = 0; mi < 2; ++mi)
#pragma unroll
        for (int ni = 0; ni < 8; ++ni)
#pragma unroll
            for (int q = 0; q < 4; ++q) c[mi][ni][q] = 0.f;

    for (int chunk = 0; chunk < 2; ++chunk) {
        int kp0 = chunk * 32;
        __syncthreads();
#pragma unroll
        for (int i = 0; i < 16; ++i) {
            int idx = i * 256 + tid;
            int r = idx >> 5, p = idx & 31;
            int gr = row0 + r;
            float2 v = (gr < nrows) ? *(const float2*)&X[(size_t)gr * 128 + (kp0 + p) * 2]
                                    : make_float2(0.f, 0.f);
            uint32_t h, l;
            cvt_hilo(v.x, v.y, h, l);
            Ahi[r * ASTR + p] = h;
            Alo[r * ASTR + p] = l;
            Bhi[r * ASTR + p] = Wthi[r * 64 + kp0 + p];
            Blo[r * ASTR + p] = Wtlo[r * 64 + kp0 + p];
        }
        __syncthreads();

        const int aB0 = (wm * 32 + g) * ASTR + tig;
        const int bB0 = (wn * 64 + g) * ASTR + tig;
#pragma unroll
        for (int ks = 0; ks < 4; ++ks) {
            int pb = ks * 8;
            uint32_t ah[2][4], al[2][4];
#pragma unroll
            for (int mi = 0; mi < 2; ++mi) {
                int ab = aB0 + mi * 16 * ASTR + pb;
                ah[mi][0] = Ahi[ab];
                ah[mi][1] = Ahi[ab + 8 * ASTR];
                ah[mi][2] = Ahi[ab + 4];
                ah[mi][3] = Ahi[ab + 8 * ASTR + 4];
                al[mi][0] = Alo[ab];
                al[mi][1] = Alo[ab + 8 * ASTR];
                al[mi][2] = Alo[ab + 4];
                al[mi][3] = Alo[ab + 8 * ASTR + 4];
            }
#pragma unroll
            for (int ni = 0; ni < 8; ++ni) {
                int bb = bB0 + ni * 8 * ASTR + pb;
                uint32_t bh0 = Bhi[bb];
                uint32_t bh1 = Bhi[bb + 4];
                uint32_t bl0 = Blo[bb];
                uint32_t bl1 = Blo[bb + 4];
#pragma unroll
                for (int mi = 0; mi < 2; ++mi) {
                    MMA_BF16(c[mi][ni][0], c[mi][ni][1], c[mi][ni][2], c[mi][ni][3],
                             ah[mi][0], ah[mi][1], ah[mi][2], ah[mi][3], bh0, bh1);
                    MMA_BF16(c[mi][ni][0], c[mi][ni][1], c[mi][ni][2], c[mi][ni][3],
                             ah[mi][0], ah[mi][1], ah[mi][2], ah[mi][3], bl0, bl1);
                    MMA_BF16(c[mi][ni][0], c[mi][ni][1], c[mi][ni][2], c[mi][ni][3],
                             al[mi][0], al[mi][1], al[mi][2], al[mi][3], bh0, bh1);
                }
            }
        }
    }

#pragma unroll
    for (int mi = 0; mi < 2; ++mi) {
        int r = row0 + wm * 32 + mi * 16 + g;
#pragma unroll
        for (int ni = 0; ni < 8; ++ni) {
            int cn = wn * 64 + ni * 8 + 2 * tig;
            if (r < nrows)
                *(float2*)&out[(size_t)r * 128 + cn] = make_float2(c[mi][ni][0], c[mi][ni][1]);
            if (r + 8 < nrows)
                *(float2*)&out[(size_t)(r + 8) * 128 + cn] = make_float2(c[mi][ni][2], c[mi][ni][3]);
        }
    }
}

// ==== CSR gather + fused attention partial ====
__global__ __launch_bounds__(256) void gather_relu(const int* __restrict__ rowptr,
                                                   const int* __restrict__ esrc,
                                                   const float* __restrict__ ews,
                                                   const float* __restrict__ S,
                                                   const float* __restrict__ b,
                                                   const float* __restrict__ wa_seg,
                                                   float* __restrict__ out,
                                                   float* __restrict__ T,
                                                   int accum)
{
    int gt   = blockIdx.x * blockDim.x + threadIdx.x;
    int node = gt >> 5;
    int lane = gt & 31;
    if (node >= N_NODES) return;

    int e0 = rowptr[node], e1 = rowptr[node + 1];
    float4 acc = make_float4(0.f, 0.f, 0.f, 0.f);

    int e = e0;
    for (; e + 3 < e1; e += 4) {
        int   s0 = __ldg(esrc + e),     s1 = __ldg(esrc + e + 1);
        int   s2 = __ldg(esrc + e + 2), s3 = __ldg(esrc + e + 3);
        float w0 = __ldg(ews + e),      w1 = __ldg(ews + e + 1);
        float w2 = __ldg(ews + e + 2),  w3 = __ldg(ews + e + 3);
        float4 v0 = ((const float4*)(S + (size_t)s0 * 128))[lane];
        float4 v1 = ((const float4*)(S + (size_t)s1 * 128))[lane];
        float4 v2 = ((const float4*)(S + (size_t)s2 * 128))[lane];
        float4 v3 = ((const float4*)(S + (size_t)s3 * 128))[lane];
        acc.x = fmaf(w0, v0.x, acc.x); acc.y = fmaf(w0, v0.y, acc.y);
        acc.z = fmaf(w0, v0.z, acc.z); acc.w = fmaf(w0, v0.w, acc.w);
        acc.x = fmaf(w1, v1.x, acc.x); acc.y = fmaf(w1, v1.y, acc.y);
        acc.z = fmaf(w1, v1.z, acc.z); acc.w = fmaf(w1, v1.w, acc.w);
        acc.x = fmaf(w2, v2.x, acc.x); acc.y = fmaf(w2, v2.y, acc.y);
        acc.z = fmaf(w2, v2.z, acc.z); acc.w = fmaf(w2, v2.w, acc.w);
        acc.x = fmaf(w3, v3.x, acc.x); acc.y = fmaf(w3, v3.y, acc.y);
        acc.z = fmaf(w3, v3.z, acc.z); acc.w = fmaf(w3, v3.w, acc.w);
    }
    for (; e < e1; ++e) {
        int   s0 = __ldg(esrc + e);
        float w0 = __ldg(ews + e);
        float4 v0 = ((const float4*)(S + (size_t)s0 * 128))[lane];
        acc.x = fmaf(w0, v0.x, acc.x); acc.y = fmaf(w0, v0.y, acc.y);
        acc.z = fmaf(w0, v0.z, acc.z); acc.w = fmaf(w0, v0.w, acc.w);
    }

    float4 bb = ((const float4*)b)[lane];
    acc.x = fmaxf(acc.x + bb.x, 0.f);
    acc.y = fmaxf(acc.y + bb.y, 0.f);
    acc.z = fmaxf(acc.z + bb.z, 0.f);
    acc.w = fmaxf(acc.w + bb.w, 0.f);
    ((float4*)(out + (size_t)node * 128))[lane] = acc;

    float4 ww = ((const float4*)wa_seg)[lane];
    float s = acc.x * ww.x + acc.y * ww.y + acc.z * ww.z + acc.w * ww.w;
#pragma unroll
    for (int off = 16; off; off >>= 1) s += __shfl_xor_sync(0xFFFFFFFFu, s, off);
    if (lane == 0) {
        if (accum) T[node] += s;
        else       T[node]  = s;
    }
}

// ---------- sc[node] = tanh( sum_e w_e * t[esrc[e]] + ba ), warp/node ----------
__global__ __launch_bounds__(256) void gather_score(const int* __restrict__ rowptr,
                                                    const int* __restrict__ esrc,
                                                    const float* __restrict__ ews,
                                                    const float* __restrict__ t,
                                                    const float* __restrict__ ba,
                                                    float* __restrict__ sc)
{
    int gt   = blockIdx.x * blockDim.x + threadIdx.x;
    int node = gt >> 5;
    int lane = gt & 31;
    if (node >= N_NODES) return;

    int e0 = rowptr[node], e1 = rowptr[node + 1];
    float s = 0.f;
    for (int e = e0 + lane; e < e1; e += 32)
        s = fmaf(__ldg(ews + e), __ldg(t + __ldg(esrc + e)), s);
#pragma unroll
    for (int off = 16; off; off >>= 1) s += __shfl_xor_sync(0xFFFFFFFFu, s, off);
    if (lane == 0) sc[node] = tanhf(s + ba[0]);
}

// ---------------- per-graph pooling ----------------
__device__ __forceinline__ int lowerb(const int* a, int n, int v)
{
    int lo = 0, hi = n;
    while (lo < hi) { int m = (lo + hi) >> 1; if (a[m] < v) lo = m + 1; else hi = m; }
    return lo;
}

__global__ __launch_bounds__(384) void pool_part(const float* __restrict__ g1,
                                                 const float* __restrict__ g2,
                                                 const float* __restrict__ g3,
                                                 const float* __restrict__ score,
                                                 const int* __restrict__ gi,
                                                 float* __restrict__ pps,
                                                 float* __restrict__ ppm,
                                                 int* __restrict__ gcnt)
{
    int b = blockIdx.x;
    int g = b >> 2, part = b & 3;
    int c = threadIdx.x;
    __shared__ int sS, sE;
    if (c == 0) sS = lowerb(gi, N_NODES, g);
    if (c == 1) sE = lowerb(gi, N_NODES, g + 1);
    __syncthreads();
    int start = sS, end = sE, len = end - start;
    int n0 = start + (len * part) / 4;
    int n1 = start + (len * (part + 1)) / 4;

    const float* base = (c < 128) ? g1 : (c < 256) ? g2 : g3;
    int cc = c & 127;

    float sum = 0.f, mx = -INFINITY;
    for (int n = n0; n < n1; ++n) {
        float v = base[(size_t)n * 128 + cc] * score[n];
        sum += v;
        mx = fmaxf(mx, v);
    }
    pps[b * 384 + c] = sum;
    ppm[b * 384 + c] = mx;
    if (part == 0 && c == 0) gcnt[g] = len;
}

__global__ __launch_bounds__(384) void pool_comb(const float* __restrict__ pps,
                                                 const float* __restrict__ ppm,
                                                 const int* __restrict__ gcnt,
                                                 float* __restrict__ pooled)
{
    int g = blockIdx.x, c = threadIdx.x;
    float sum = 0.f, mx = -INFINITY;
#pragma unroll
    for (int p = 0; p < 4; ++p) {
        sum += pps[(g * 4 + p) * 384 + c];
        mx = fmaxf(mx, ppm[(g * 4 + p) * 384 + c]);
    }
    float cnt = (float)gcnt[g];
    pooled[g * 768 + c]       = sum / fmaxf(cnt, 1.f);
    pooled[g * 768 + 384 + c] = mx;
}

// ---------------- out = relu(pooled @ Wf + bf) ----------------
__global__ __launch_bounds__(128) void final_k(const float* __restrict__ pooled,
                                               const float* __restrict__ Wf,
                                               const float* __restrict__ bf,
                                               float* __restrict__ out)
{
    int g = blockIdx.x, c = threadIdx.x;
    __shared__ float pr[768];
    for (int i = c; i < 768; i += 128) pr[i] = pooled[g * 768 + i];
    __syncthreads();
    float acc = bf[c];
#pragma unroll 8
    for (int k = 0; k < 768; ++k) acc = fmaf(pr[k], Wf[k * 128 + c], acc);
    out[g * 128 + c] = fmaxf(acc, 0.f);
}

// ---------------- launch ----------------
extern "C" void kernel_launch(void* const* d_in, const int* in_sizes, int n_in,
                              void* d_out, int out_size)
{
    const int*   ei  = (const int*)d_in[0];
    const float* ew  = (const float*)d_in[1];
    const float* X   = (const float*)d_in[2];
    const int*   gi  = (const int*)d_in[3];
    const float* W1  = (const float*)d_in[4];
    const float* b1  = (const float*)d_in[5];
    const float* W2  = (const float*)d_in[6];
    const float* b2  = (const float*)d_in[7];
    const float* W3  = (const float*)d_in[8];
    const float* b3  = (const float*)d_in[9];
    const float* wa  = (const float*)d_in[10];
    const float* ba  = (const float*)d_in[11];
    const float* Wf  = (const float*)d_in[12];
    const float* bf  = (const float*)d_in[13];
    float* out = (float*)d_out;

    const int* src = ei;
    const int* dst = ei + N_EDGES;

    static int inited = 0;
    static cudaStream_t s2;
    static cudaEvent_t evFork, evJoin;
    if (!inited) {
        cudaFuncSetAttribute(gemm_bf16x3, cudaFuncAttributeMaxDynamicSharedMemorySize, GEMM_SMEM);
        cudaStreamCreateWithFlags(&s2, cudaStreamNonBlocking);
        cudaEventCreateWithFlags(&evFork, cudaEventDisableTiming);
        cudaEventCreateWithFlags(&evJoin, cudaEventDisableTiming);
        inited = 1;
    }

    void *pS, *pG1, *pG2, *pG3, *pT, *pSC, *pPOOL;
    void *pCNT, *pRP, *pCUR, *pESRC, *pEWS, *pPPS, *pPPM, *pGC, *pWH, *pWL;
    cudaGetSymbolAddress(&pS,   d_S);
    cudaGetSymbolAddress(&pG1,  d_G1);
    cudaGetSymbolAddress(&pG2,  d_G2);
    cudaGetSymbolAddress(&pG3,  d_G3);
    cudaGetSymbolAddress(&pT,   d_T);
    cudaGetSymbolAddress(&pSC,  d_SC);
    cudaGetSymbolAddress(&pPOOL, d_POOL);
    cudaGetSymbolAddress(&pCNT, d_CNT);
    cudaGetSymbolAddress(&pRP,  d_ROWPTR);
    cudaGetSymbolAddress(&pCUR, d_CUR);
    cudaGetSymbolAddress(&pESRC, d_ESRC);
    cudaGetSymbolAddress(&pEWS,  d_EWS);
    cudaGetSymbolAddress(&pPPS, d_PPS);
    cudaGetSymbolAddress(&pPPM, d_PPM);
    cudaGetSymbolAddress(&pGC,  d_GCNT);
    cudaGetSymbolAddress(&pWH,  d_WH);
    cudaGetSymbolAddress(&pWL,  d_WL);

    float* S   = (float*)pS;
    float* G1  = (float*)pG1;
    float* G2  = (float*)pG2;
    float* G3  = (float*)pG3;
    float* T   = (float*)pT;
    float* SC  = (float*)pSC;
    float* PO  = (float*)pPOOL;
    int*   CNT = (int*)pCNT;
    int*   RP  = (int*)pRP;
    int*   CUR = (int*)pCUR;
    int*   ESRC = (int*)pESRC;
    float* EWS  = (float*)pEWS;
    float* PPS = (float*)pPPS;
    float* PPM = (float*)pPPM;
    int*   GC  = (int*)pGC;
    uint32_t* WH = (uint32_t*)pWH;
    uint32_t* WL = (uint32_t*)pWL;

    const int gemm_grid = (N_NODES + 127) / 128;
    const int edge_grid = (N_EDGES + 255) / 256;
    const int warp_grid = (N_NODES * 32 + 255) / 256;

    // ---- fork: CSR build on s2, concurrent with wprep + gemm1 on main ----
    cudaEventRecord(evFork, 0);
    cudaStreamWaitEvent(s2, evFork, 0);

    cudaMemsetAsync(CNT, 0, N_NODES * sizeof(int), s2);
    csr_count<<<edge_grid, 256, 0, s2>>>(dst, CNT);
    csr_scan<<<1, 1024, 0, s2>>>(CNT, RP, CUR);
    csr_fill<<<edge_grid, 256, 0, s2>>>(src, dst, ew, CUR, ESRC, EWS);
    cudaEventRecord(evJoin, s2);

    // ---- main stream: W conversion + gemm1 (independent of CSR) ----
    wprep<<<32, 256>>>(W1, WH,          WL);
    wprep<<<32, 256>>>(W2, WH + 8192,   WL + 8192);
    wprep<<<32, 256>>>(W3, WH + 16384,  WL + 16384);
    gemm_bf16x3<<<gemm_grid, 256, GEMM_SMEM>>>(X, WH, WL, S, N_NODES);

    // ---- join: gathers need CSR ----
    cudaStreamWaitEvent(0, evJoin, 0);

    gather_relu<<<warp_grid, 256>>>(RP, ESRC, EWS, S, b1, wa,       G1, T, 0);
    gemm_bf16x3<<<gemm_grid, 256, GEMM_SMEM>>>(G1, WH + 8192, WL + 8192, S, N_NODES);
    gather_relu<<<warp_grid, 256>>>(RP, ESRC, EWS, S, b2, wa + 128, G2, T, 1);
    gemm_bf16x3<<<gemm_grid, 256, GEMM_SMEM>>>(G2, WH + 16384, WL + 16384, S, N_NODES);
    gather_relu<<<warp_grid, 256>>>(RP, ESRC, EWS, S, b3, wa + 256, G3, T, 1);

    // ---- attention score ----
    gather_score<<<warp_grid, 256>>>(RP, ESRC, EWS, T, ba, SC);

    // ---- pooling + final FC ----
    pool_part<<<N_GRAPHS * 4, 384>>>(G1, G2, G3, SC, gi, PPS, PPM, GC);
    pool_comb<<<N_GRAPHS, 384>>>(PPS, PPM, GC, PO);
    final_k<<<N_GRAPHS, 128>>>(PO, Wf, bf, out);

    (void)in_sizes; (void)n_in; (void)out_size;
}

// round 10
// speedup vs baseline: 2.1675x; 1.0796x over previous
#include <cuda_runtime.h>
#include <cuda_bf16.h>
#include <cuda_fp16.h>
#include <math.h>
#include <stdint.h>

#define N_NODES 50000
#define N_EDGES 800000
#define HID     128
#define N_GRAPHS 64

// ---------------- scratch (allocation-free: __device__ globals) ----------------
__device__ __half d_S16[N_NODES * HID];   // GEMM output in fp16 (gather source)
__device__ float d_G1[N_NODES * HID];
__device__ float d_G2[N_NODES * HID];
__device__ float d_G3[N_NODES * HID];
__device__ float d_T [N_NODES];
__device__ float d_SC[N_NODES];
__device__ float d_POOL[N_GRAPHS * 6 * HID];
// CSR scratch
__device__ int   d_CNT[N_NODES];
__device__ int   d_ROWPTR[N_NODES + 1];
__device__ int   d_CUR[N_NODES];
__device__ int   d_ESRC[N_EDGES];
__device__ float d_EWS [N_EDGES];
// pooling partials
__device__ float d_PPS[N_GRAPHS * 4 * 384];
__device__ float d_PPM[N_GRAPHS * 4 * 384];
__device__ int   d_GCNT[N_GRAPHS];
// W converted: transposed [n][kpair] packed bf16x2, hi/lo, 3 layers
__device__ uint32_t d_WH[3][128 * 64];
__device__ uint32_t d_WL[3][128 * 64];

// ---- bf16 hi/lo split + pack ----
__device__ __forceinline__ void cvt_hilo(float x, float y, uint32_t& hi, uint32_t& lo)
{
    __nv_bfloat16 h0 = __float2bfloat16(x);
    __nv_bfloat16 h1 = __float2bfloat16(y);
    float rx = x - __bfloat162float(h0);
    float ry = y - __bfloat162float(h1);
    __nv_bfloat16 l0 = __float2bfloat16(rx);
    __nv_bfloat16 l1 = __float2bfloat16(ry);
    hi = ((uint32_t)__bfloat16_as_ushort(h1) << 16) | (uint32_t)__bfloat16_as_ushort(h0);
    lo = ((uint32_t)__bfloat16_as_ushort(l1) << 16) | (uint32_t)__bfloat16_as_ushort(l0);
}

#define MMA_BF16(c0,c1,c2,c3, a0,a1,a2,a3, b0,b1) \
    asm("mma.sync.aligned.m16n8k16.row.col.f32.bf16.bf16.f32 " \
        "{%0,%1,%2,%3}, {%4,%5,%6,%7}, {%8,%9}, {%0,%1,%2,%3};" \
        : "+f"(c0), "+f"(c1), "+f"(c2), "+f"(c3) \
        : "r"(a0), "r"(a1), "r"(a2), "r"(a3), "r"(b0), "r"(b1))

// ================= W prep: W[k][n] fp32 -> Wt[n][kpair] bf16x2 hi/lo =================
__global__ __launch_bounds__(256) void wprep(const float* __restrict__ W,
                                             uint32_t* __restrict__ hi,
                                             uint32_t* __restrict__ lo)
{
    int idx = blockIdx.x * blockDim.x + threadIdx.x;
    if (idx >= 128 * 64) return;
    int n = idx >> 6, p = idx & 63;
    float w0 = W[(2 * p) * 128 + n];
    float w1 = W[(2 * p + 1) * 128 + n];
    uint32_t h, l;
    cvt_hilo(w0, w1, h, l);
    hi[n * 64 + p] = h;
    lo[n * 64 + p] = l;
}

// ================= CSR build =================
__global__ __launch_bounds__(256) void csr_count(const int* __restrict__ dst, int* __restrict__ cnt)
{
    int e = blockIdx.x * blockDim.x + threadIdx.x;
    if (e < N_EDGES) atomicAdd(&cnt[dst[e]], 1);
}

__global__ __launch_bounds__(1024) void csr_scan(const int* __restrict__ cnt,
                                                 int* __restrict__ rowptr,
                                                 int* __restrict__ cur)
{
    __shared__ int warpsum[32];
    __shared__ int carry;
    int t = threadIdx.x, lane = t & 31, w = t >> 5;
    if (t == 0) carry = 0;
    __syncthreads();
    for (int base = 0; base < N_NODES; base += 1024) {
        int i = base + t;
        int v = (i < N_NODES) ? cnt[i] : 0;
        int x = v;
#pragma unroll
        for (int off = 1; off < 32; off <<= 1) {
            int y = __shfl_up_sync(0xFFFFFFFFu, x, off);
            if (lane >= off) x += y;
        }
        if (lane == 31) warpsum[w] = x;
        __syncthreads();
        if (w == 0) {
            int s = warpsum[lane];
#pragma unroll
            for (int off = 1; off < 32; off <<= 1) {
                int y = __shfl_up_sync(0xFFFFFFFFu, s, off);
                if (lane >= off) s += y;
            }
            warpsum[lane] = s;
        }
        __syncthreads();
        int incl = x + (w > 0 ? warpsum[w - 1] : 0);
        if (i < N_NODES) {
            int ex = carry + incl - v;
            rowptr[i] = ex;
            cur[i]    = ex;
        }
        __syncthreads();
        if (t == 1023) carry += warpsum[31];
        __syncthreads();
    }
    if (t == 0) rowptr[N_NODES] = carry;
}

__global__ __launch_bounds__(256) void csr_fill(const int* __restrict__ src,
                                                const int* __restrict__ dst,
                                                const float* __restrict__ ew,
                                                int* __restrict__ cur,
                                                int* __restrict__ esrc,
                                                float* __restrict__ ews)
{
    int e = blockIdx.x * blockDim.x + threadIdx.x;
    if (e >= N_EDGES) return;
    int d = dst[e];
    int p = atomicAdd(&cur[d], 1);
    esrc[p] = src[e];
    ews[p]  = ew[e];
}

// ===== GEMM via bf16x3 tensor cores -> fp16 output =====
#define ASTR 36
#define SM_CH (128 * ASTR)
#define GEMM_SMEM (4 * SM_CH * 4)

__global__ __launch_bounds__(256, 2) void gemm_bf16x3(const float* __restrict__ X,
                                                      const uint32_t* __restrict__ Wthi,
                                                      const uint32_t* __restrict__ Wtlo,
                                                      __half* __restrict__ out, int nrows)
{
    extern __shared__ uint32_t sm[];
    uint32_t* Ahi = sm;
    uint32_t* Alo = sm + SM_CH;
    uint32_t* Bhi = sm + 2 * SM_CH;
    uint32_t* Blo = sm + 3 * SM_CH;

    const int tid  = threadIdx.x;
    const int row0 = blockIdx.x * 128;
    const int warp = tid >> 5, lane = tid & 31;
    const int g    = lane >> 2, tig = lane & 3;
    const int wm   = warp >> 1, wn = warp & 1;

    float c[2][8][4];
#pragma unroll
    for (int mi = 0; mi < 2; ++mi)
#pragma unroll
        for (int ni = 0; ni < 8; ++ni)
#pragma unroll
            for (int q = 0; q < 4; ++q) c[mi][ni][q] = 0.f;

    for (int chunk = 0; chunk < 2; ++chunk) {
        int kp0 = chunk * 32;
        __syncthreads();
#pragma unroll
        for (int i = 0; i < 16; ++i) {
            int idx = i * 256 + tid;
            int r = idx >> 5, p = idx & 31;
            int gr = row0 + r;
            float2 v = (gr < nrows) ? *(const float2*)&X[(size_t)gr * 128 + (kp0 + p) * 2]
                                    : make_float2(0.f, 0.f);
            uint32_t h, l;
            cvt_hilo(v.x, v.y, h, l);
            Ahi[r * ASTR + p] = h;
            Alo[r * ASTR + p] = l;
            Bhi[r * ASTR + p] = Wthi[r * 64 + kp0 + p];
            Blo[r * ASTR + p] = Wtlo[r * 64 + kp0 + p];
        }
        __syncthreads();

        const int aB0 = (wm * 32 + g) * ASTR + tig;
        const int bB0 = (wn * 64 + g) * ASTR + tig;
#pragma unroll
        for (int ks = 0; ks < 4; ++ks) {
            int pb = ks * 8;
            uint32_t ah[2][4], al[2][4];
#pragma unroll
            for (int mi = 0; mi < 2; ++mi) {
                int ab = aB0 + mi * 16 * ASTR + pb;
                ah[mi][0] = Ahi[ab];
                ah[mi][1] = Ahi[ab + 8 * ASTR];
                ah[mi][2] = Ahi[ab + 4];
                ah[mi][3] = Ahi[ab + 8 * ASTR + 4];
                al[mi][0] = Alo[ab];
                al[mi][1] = Alo[ab + 8 * ASTR];
                al[mi][2] = Alo[ab + 4];
                al[mi][3] = Alo[ab + 8 * ASTR + 4];
            }
#pragma unroll
            for (int ni = 0; ni < 8; ++ni) {
                int bb = bB0 + ni * 8 * ASTR + pb;
                uint32_t bh0 = Bhi[bb];
                uint32_t bh1 = Bhi[bb + 4];
                uint32_t bl0 = Blo[bb];
                uint32_t bl1 = Blo[bb + 4];
#pragma unroll
                for (int mi = 0; mi < 2; ++mi) {
                    MMA_BF16(c[mi][ni][0], c[mi][ni][1], c[mi][ni][2], c[mi][ni][3],
                             ah[mi][0], ah[mi][1], ah[mi][2], ah[mi][3], bh0, bh1);
                    MMA_BF16(c[mi][ni][0], c[mi][ni][1], c[mi][ni][2], c[mi][ni][3],
                             ah[mi][0], ah[mi][1], ah[mi][2], ah[mi][3], bl0, bl1);
                    MMA_BF16(c[mi][ni][0], c[mi][ni][1], c[mi][ni][2], c[mi][ni][3],
                             al[mi][0], al[mi][1], al[mi][2], al[mi][3], bh0, bh1);
                }
            }
        }
    }

    // store fp16: c0,c1 -> (row, 2tig..+1), c2,c3 -> (row+8)
#pragma unroll
    for (int mi = 0; mi < 2; ++mi) {
        int r = row0 + wm * 32 + mi * 16 + g;
#pragma unroll
        for (int ni = 0; ni < 8; ++ni) {
            int cn = wn * 64 + ni * 8 + 2 * tig;
            if (r < nrows)
                *(__half2*)&out[(size_t)r * 128 + cn] = __floats2half2_rn(c[mi][ni][0], c[mi][ni][1]);
            if (r + 8 < nrows)
                *(__half2*)&out[(size_t)(r + 8) * 128 + cn] = __floats2half2_rn(c[mi][ni][2], c[mi][ni][3]);
        }
    }
}

// ==== CSR gather (fp16 source) + fused attention partial ====
__device__ __forceinline__ void acc_row(float4& acc, const __half* __restrict__ S,
                                        int s, int lane, float w)
{
    uint2 u = ((const uint2*)(S + (size_t)s * 128))[lane];
    __half2 p0 = *(__half2*)&u.x;
    __half2 p1 = *(__half2*)&u.y;
    float2 f0 = __half22float2(p0);
    float2 f1 = __half22float2(p1);
    acc.x = fmaf(w, f0.x, acc.x);
    acc.y = fmaf(w, f0.y, acc.y);
    acc.z = fmaf(w, f1.x, acc.z);
    acc.w = fmaf(w, f1.y, acc.w);
}

__global__ __launch_bounds__(256) void gather_relu(const int* __restrict__ rowptr,
                                                   const int* __restrict__ esrc,
                                                   const float* __restrict__ ews,
                                                   const __half* __restrict__ S,
                                                   const float* __restrict__ b,
                                                   const float* __restrict__ wa_seg,
                                                   float* __restrict__ out,
                                                   float* __restrict__ T,
                                                   int accum)
{
    int gt   = blockIdx.x * blockDim.x + threadIdx.x;
    int node = gt >> 5;
    int lane = gt & 31;
    if (node >= N_NODES) return;

    int e0 = rowptr[node], e1 = rowptr[node + 1];
    float4 acc = make_float4(0.f, 0.f, 0.f, 0.f);

    int e = e0;
    for (; e + 3 < e1; e += 4) {
        int   s0 = __ldg(esrc + e),     s1 = __ldg(esrc + e + 1);
        int   s2 = __ldg(esrc + e + 2), s3 = __ldg(esrc + e + 3);
        float w0 = __ldg(ews + e),      w1 = __ldg(ews + e + 1);
        float w2 = __ldg(ews + e + 2),  w3 = __ldg(ews + e + 3);
        acc_row(acc, S, s0, lane, w0);
        acc_row(acc, S, s1, lane, w1);
        acc_row(acc, S, s2, lane, w2);
        acc_row(acc, S, s3, lane, w3);
    }
    for (; e < e1; ++e) {
        int   s0 = __ldg(esrc + e);
        float w0 = __ldg(ews + e);
        acc_row(acc, S, s0, lane, w0);
    }

    float4 bb = ((const float4*)b)[lane];
    acc.x = fmaxf(acc.x + bb.x, 0.f);
    acc.y = fmaxf(acc.y + bb.y, 0.f);
    acc.z = fmaxf(acc.z + bb.z, 0.f);
    acc.w = fmaxf(acc.w + bb.w, 0.f);
    ((float4*)(out + (size_t)node * 128))[lane] = acc;

    float4 ww = ((const float4*)wa_seg)[lane];
    float s = acc.x * ww.x + acc.y * ww.y + acc.z * ww.z + acc.w * ww.w;
#pragma unroll
    for (int off = 16; off; off >>= 1) s += __shfl_xor_sync(0xFFFFFFFFu, s, off);
    if (lane == 0) {
        if (accum) T[node] += s;
        else       T[node]  = s;
    }
}

// ---------- sc[node] = tanh( sum_e w_e * t[esrc[e]] + ba ), warp/node ----------
__global__ __launch_bounds__(256) void gather_score(const int* __restrict__ rowptr,
                                                    const int* __restrict__ esrc,
                                                    const float* __restrict__ ews,
                                                    const float* __restrict__ t,
                                                    const float* __restrict__ ba,
                                                    float* __restrict__ sc)
{
    int gt   = blockIdx.x * blockDim.x + threadIdx.x;
    int node = gt >> 5;
    int lane = gt & 31;
    if (node >= N_NODES) return;

    int e0 = rowptr[node], e1 = rowptr[node + 1];
    float s = 0.f;
    for (int e = e0 + lane; e < e1; e += 32)
        s = fmaf(__ldg(ews + e), __ldg(t + __ldg(esrc + e)), s);
#pragma unroll
    for (int off = 16; off; off >>= 1) s += __shfl_xor_sync(0xFFFFFFFFu, s, off);
    if (lane == 0) sc[node] = tanhf(s + ba[0]);
}

// ---------------- per-graph pooling ----------------
__device__ __forceinline__ int lowerb(const int* a, int n, int v)
{
    int lo = 0, hi = n;
    while (lo < hi) { int m = (lo + hi) >> 1; if (a[m] < v) lo = m + 1; else hi = m; }
    return lo;
}

__global__ __launch_bounds__(384) void pool_part(const float* __restrict__ g1,
                                                 const float* __restrict__ g2,
                                                 const float* __restrict__ g3,
                                                 const float* __restrict__ score,
                                                 const int* __restrict__ gi,
                                                 float* __restrict__ pps,
                                                 float* __restrict__ ppm,
                                                 int* __restrict__ gcnt)
{
    int b = blockIdx.x;
    int g = b >> 2, part = b & 3;
    int c = threadIdx.x;
    __shared__ int sS, sE;
    if (c == 0) sS = lowerb(gi, N_NODES, g);
    if (c == 1) sE = lowerb(gi, N_NODES, g + 1);
    __syncthreads();
    int start = sS, end = sE, len = end - start;
    int n0 = start + (len * part) / 4;
    int n1 = start + (len * (part + 1)) / 4;

    const float* base = (c < 128) ? g1 : (c < 256) ? g2 : g3;
    int cc = c & 127;

    float sum = 0.f, mx = -INFINITY;
    for (int n = n0; n < n1; ++n) {
        float v = base[(size_t)n * 128 + cc] * score[n];
        sum += v;
        mx = fmaxf(mx, v);
    }
    pps[b * 384 + c] = sum;
    ppm[b * 384 + c] = mx;
    if (part == 0 && c == 0) gcnt[g] = len;
}

__global__ __launch_bounds__(384) void pool_comb(const float* __restrict__ pps,
                                                 const float* __restrict__ ppm,
                                                 const int* __restrict__ gcnt,
                                                 float* __restrict__ pooled)
{
    int g = blockIdx.x, c = threadIdx.x;
    float sum = 0.f, mx = -INFINITY;
#pragma unroll
    for (int p = 0; p < 4; ++p) {
        sum += pps[(g * 4 + p) * 384 + c];
        mx = fmaxf(mx, ppm[(g * 4 + p) * 384 + c]);
    }
    float cnt = (float)gcnt[g];
    pooled[g * 768 + c]       = sum / fmaxf(cnt, 1.f);
    pooled[g * 768 + 384 + c] = mx;
}

// ---------------- out = relu(pooled @ Wf + bf) ----------------
__global__ __launch_bounds__(128) void final_k(const float* __restrict__ pooled,
                                               const float* __restrict__ Wf,
                                               const float* __restrict__ bf,
                                               float* __restrict__ out)
{
    int g = blockIdx.x, c = threadIdx.x;
    __shared__ float pr[768];
    for (int i = c; i < 768; i += 128) pr[i] = pooled[g * 768 + i];
    __syncthreads();
    float acc = bf[c];
#pragma unroll 8
    for (int k = 0; k < 768; ++k) acc = fmaf(pr[k], Wf[k * 128 + c], acc);
    out[g * 128 + c] = fmaxf(acc, 0.f);
}

// ---------------- launch ----------------
extern "C" void kernel_launch(void* const* d_in, const int* in_sizes, int n_in,
                              void* d_out, int out_size)
{
    const int*   ei  = (const int*)d_in[0];
    const float* ew  = (const float*)d_in[1];
    const float* X   = (const float*)d_in[2];
    const int*   gi  = (const int*)d_in[3];
    const float* W1  = (const float*)d_in[4];
    const float* b1  = (const float*)d_in[5];
    const float* W2  = (const float*)d_in[6];
    const float* b2  = (const float*)d_in[7];
    const float* W3  = (const float*)d_in[8];
    const float* b3  = (const float*)d_in[9];
    const float* wa  = (const float*)d_in[10];
    const float* ba  = (const float*)d_in[11];
    const float* Wf  = (const float*)d_in[12];
    const float* bf  = (const float*)d_in[13];
    float* out = (float*)d_out;

    const int* src = ei;
    const int* dst = ei + N_EDGES;

    static int inited = 0;
    static cudaStream_t s2;
    static cudaEvent_t evFork, evJoin;
    if (!inited) {
        cudaFuncSetAttribute(gemm_bf16x3, cudaFuncAttributeMaxDynamicSharedMemorySize, GEMM_SMEM);
        cudaStreamCreateWithFlags(&s2, cudaStreamNonBlocking);
        cudaEventCreateWithFlags(&evFork, cudaEventDisableTiming);
        cudaEventCreateWithFlags(&evJoin, cudaEventDisableTiming);
        inited = 1;
    }

    void *pS, *pG1, *pG2, *pG3, *pT, *pSC, *pPOOL;
    void *pCNT, *pRP, *pCUR, *pESRC, *pEWS, *pPPS, *pPPM, *pGC, *pWH, *pWL;
    cudaGetSymbolAddress(&pS,   d_S16);
    cudaGetSymbolAddress(&pG1,  d_G1);
    cudaGetSymbolAddress(&pG2,  d_G2);
    cudaGetSymbolAddress(&pG3,  d_G3);
    cudaGetSymbolAddress(&pT,   d_T);
    cudaGetSymbolAddress(&pSC,  d_SC);
    cudaGetSymbolAddress(&pPOOL, d_POOL);
    cudaGetSymbolAddress(&pCNT, d_CNT);
    cudaGetSymbolAddress(&pRP,  d_ROWPTR);
    cudaGetSymbolAddress(&pCUR, d_CUR);
    cudaGetSymbolAddress(&pESRC, d_ESRC);
    cudaGetSymbolAddress(&pEWS,  d_EWS);
    cudaGetSymbolAddress(&pPPS, d_PPS);
    cudaGetSymbolAddress(&pPPM, d_PPM);
    cudaGetSymbolAddress(&pGC,  d_GCNT);
    cudaGetSymbolAddress(&pWH,  d_WH);
    cudaGetSymbolAddress(&pWL,  d_WL);

    __half* S  = (__half*)pS;
    float* G1  = (float*)pG1;
    float* G2  = (float*)pG2;
    float* G3  = (float*)pG3;
    float* T   = (float*)pT;
    float* SC  = (float*)pSC;
    float* PO  = (float*)pPOOL;
    int*   CNT = (int*)pCNT;
    int*   RP  = (int*)pRP;
    int*   CUR = (int*)pCUR;
    int*   ESRC = (int*)pESRC;
    float* EWS  = (float*)pEWS;
    float* PPS = (float*)pPPS;
    float* PPM = (float*)pPPM;
    int*   GC  = (int*)pGC;
    uint32_t* WH = (uint32_t*)pWH;
    uint32_t* WL = (uint32_t*)pWL;

    const int gemm_grid = (N_NODES + 127) / 128;
    const int edge_grid = (N_EDGES + 255) / 256;
    const int warp_grid = (N_NODES * 32 + 255) / 256;

    // ---- fork: CSR build on s2, concurrent with wprep + gemm1 on main ----
    cudaEventRecord(evFork, 0);
    cudaStreamWaitEvent(s2, evFork, 0);

    cudaMemsetAsync(CNT, 0, N_NODES * sizeof(int), s2);
    csr_count<<<edge_grid, 256, 0, s2>>>(dst, CNT);
    csr_scan<<<1, 1024, 0, s2>>>(CNT, RP, CUR);
    csr_fill<<<edge_grid, 256, 0, s2>>>(src, dst, ew, CUR, ESRC, EWS);
    cudaEventRecord(evJoin, s2);

    // ---- main stream: W conversion + gemm1 ----
    wprep<<<32, 256>>>(W1, WH,          WL);
    wprep<<<32, 256>>>(W2, WH + 8192,   WL + 8192);
    wprep<<<32, 256>>>(W3, WH + 16384,  WL + 16384);
    gemm_bf16x3<<<gemm_grid, 256, GEMM_SMEM>>>(X, WH, WL, S, N_NODES);

    // ---- join: gathers need CSR ----
    cudaStreamWaitEvent(0, evJoin, 0);

    gather_relu<<<warp_grid, 256>>>(RP, ESRC, EWS, S, b1, wa,       G1, T, 0);
    gemm_bf16x3<<<gemm_grid, 256, GEMM_SMEM>>>(G1, WH + 8192, WL + 8192, S, N_NODES);
    gather_relu<<<warp_grid, 256>>>(RP, ESRC, EWS, S, b2, wa + 128, G2, T, 1);
    gemm_bf16x3<<<gemm_grid, 256, GEMM_SMEM>>>(G2, WH + 16384, WL + 16384, S, N_NODES);
    gather_relu<<<warp_grid, 256>>>(RP, ESRC, EWS, S, b3, wa + 256, G3, T, 1);

    // ---- attention score ----
    gather_score<<<warp_grid, 256>>>(RP, ESRC, EWS, T, ba, SC);

    // ---- pooling + final FC ----
    pool_part<<<N_GRAPHS * 4, 384>>>(G1, G2, G3, SC, gi, PPS, PPM, GC);
    pool_comb<<<N_GRAPHS, 384>>>(PPS, PPM, GC, PO);
    final_k<<<N_GRAPHS, 128>>>(PO, Wf, bf, out);

    (void)in_sizes; (void)n_in; (void)out_size;
}

// round 11
// speedup vs baseline: 2.2899x; 1.0565x over previous
#include <cuda_runtime.h>
#include <cuda_bf16.h>
#include <cuda_fp16.h>
#include <math.h>
#include <stdint.h>

#define N_NODES 50000
#define N_EDGES 800000
#define HID     128
#define N_GRAPHS 64

// ---------------- scratch (allocation-free: __device__ globals) ----------------
__device__ __half d_S16[N_NODES * HID];   // GEMM output (gather source), fp16
__device__ __half d_G1[N_NODES * HID];    // layer outputs, fp16
__device__ __half d_G2[N_NODES * HID];
__device__ __half d_G3[N_NODES * HID];
__device__ float d_T [N_NODES];
__device__ float d_SC[N_NODES];
__device__ float d_POOL[N_GRAPHS * 6 * HID];
// CSR scratch
__device__ int   d_CNT[N_NODES];
__device__ int   d_ROWPTR[N_NODES + 1];
__device__ int   d_CUR[N_NODES];
__device__ int   d_ESRC[N_EDGES];
__device__ float d_EWS [N_EDGES];
// pooling partials
__device__ float d_PPS[N_GRAPHS * 4 * 384];
__device__ float d_PPM[N_GRAPHS * 4 * 384];
__device__ int   d_GCNT[N_GRAPHS];
// W converted: transposed [n][kpair] packed bf16x2, hi/lo, 3 layers
__device__ uint32_t d_WH[3][128 * 64];
__device__ uint32_t d_WL[3][128 * 64];

// ---- bf16 hi/lo split + pack ----
__device__ __forceinline__ void cvt_hilo(float x, float y, uint32_t& hi, uint32_t& lo)
{
    __nv_bfloat16 h0 = __float2bfloat16(x);
    __nv_bfloat16 h1 = __float2bfloat16(y);
    float rx = x - __bfloat162float(h0);
    float ry = y - __bfloat162float(h1);
    __nv_bfloat16 l0 = __float2bfloat16(rx);
    __nv_bfloat16 l1 = __float2bfloat16(ry);
    hi = ((uint32_t)__bfloat16_as_ushort(h1) << 16) | (uint32_t)__bfloat16_as_ushort(h0);
    lo = ((uint32_t)__bfloat16_as_ushort(l1) << 16) | (uint32_t)__bfloat16_as_ushort(l0);
}

#define MMA_BF16(c0,c1,c2,c3, a0,a1,a2,a3, b0,b1) \
    asm("mma.sync.aligned.m16n8k16.row.col.f32.bf16.bf16.f32 " \
        "{%0,%1,%2,%3}, {%4,%5,%6,%7}, {%8,%9}, {%0,%1,%2,%3};" \
        : "+f"(c0), "+f"(c1), "+f"(c2), "+f"(c3) \
        : "r"(a0), "r"(a1), "r"(a2), "r"(a3), "r"(b0), "r"(b1))

// ================= W prep =================
__global__ __launch_bounds__(256) void wprep(const float* __restrict__ W,
                                             uint32_t* __restrict__ hi,
                                             uint32_t* __restrict__ lo)
{
    int idx = blockIdx.x * blockDim.x + threadIdx.x;
    if (idx >= 128 * 64) return;
    int n = idx >> 6, p = idx & 63;
    float w0 = W[(2 * p) * 128 + n];
    float w1 = W[(2 * p + 1) * 128 + n];
    uint32_t h, l;
    cvt_hilo(w0, w1, h, l);
    hi[n * 64 + p] = h;
    lo[n * 64 + p] = l;
}

// ================= CSR build =================
__global__ __launch_bounds__(256) void csr_count(const int* __restrict__ dst, int* __restrict__ cnt)
{
    int e = blockIdx.x * blockDim.x + threadIdx.x;
    if (e < N_EDGES) atomicAdd(&cnt[dst[e]], 1);
}

__global__ __launch_bounds__(1024) void csr_scan(const int* __restrict__ cnt,
                                                 int* __restrict__ rowptr,
                                                 int* __restrict__ cur)
{
    __shared__ int warpsum[32];
    __shared__ int carry;
    int t = threadIdx.x, lane = t & 31, w = t >> 5;
    if (t == 0) carry = 0;
    __syncthreads();
    for (int base = 0; base < N_NODES; base += 1024) {
        int i = base + t;
        int v = (i < N_NODES) ? cnt[i] : 0;
        int x = v;
#pragma unroll
        for (int off = 1; off < 32; off <<= 1) {
            int y = __shfl_up_sync(0xFFFFFFFFu, x, off);
            if (lane >= off) x += y;
        }
        if (lane == 31) warpsum[w] = x;
        __syncthreads();
        if (w == 0) {
            int s = warpsum[lane];
#pragma unroll
            for (int off = 1; off < 32; off <<= 1) {
                int y = __shfl_up_sync(0xFFFFFFFFu, s, off);
                if (lane >= off) s += y;
            }
            warpsum[lane] = s;
        }
        __syncthreads();
        int incl = x + (w > 0 ? warpsum[w - 1] : 0);
        if (i < N_NODES) {
            int ex = carry + incl - v;
            rowptr[i] = ex;
            cur[i]    = ex;
        }
        __syncthreads();
        if (t == 1023) carry += warpsum[31];
        __syncthreads();
    }
    if (t == 0) rowptr[N_NODES] = carry;
}

__global__ __launch_bounds__(256) void csr_fill(const int* __restrict__ src,
                                                const int* __restrict__ dst,
                                                const float* __restrict__ ew,
                                                int* __restrict__ cur,
                                                int* __restrict__ esrc,
                                                float* __restrict__ ews)
{
    int e = blockIdx.x * blockDim.x + threadIdx.x;
    if (e >= N_EDGES) return;
    int d = dst[e];
    int p = atomicAdd(&cur[d], 1);
    esrc[p] = src[e];
    ews[p]  = ew[e];
}

// ===== GEMM via bf16x3 tensor cores; templated input (fp32 X / fp16 G) =====
#define ASTR 36
#define SM_CH (128 * ASTR)
#define GEMM_SMEM (4 * SM_CH * 4)

template <typename TIn>
__device__ __forceinline__ float2 load_pair(const TIn* X, size_t off);
template <>
__device__ __forceinline__ float2 load_pair<float>(const float* X, size_t off)
{
    return *(const float2*)(X + off);
}
template <>
__device__ __forceinline__ float2 load_pair<__half>(const __half* X, size_t off)
{
    __half2 h = *(const __half2*)(X + off);
    return __half22float2(h);
}

template <typename TIn>
__global__ __launch_bounds__(256, 2) void gemm_bf16x3(const TIn* __restrict__ X,
                                                      const uint32_t* __restrict__ Wthi,
                                                      const uint32_t* __restrict__ Wtlo,
                                                      __half* __restrict__ out, int nrows)
{
    extern __shared__ uint32_t sm[];
    uint32_t* Ahi = sm;
    uint32_t* Alo = sm + SM_CH;
    uint32_t* Bhi = sm + 2 * SM_CH;
    uint32_t* Blo = sm + 3 * SM_CH;

    const int tid  = threadIdx.x;
    const int row0 = blockIdx.x * 128;
    const int warp = tid >> 5, lane = tid & 31;
    const int g    = lane >> 2, tig = lane & 3;
    const int wm   = warp >> 1, wn = warp & 1;

    float c[2][8][4];
#pragma unroll
    for (int mi = 0; mi < 2; ++mi)
#pragma unroll
        for (int ni = 0; ni < 8; ++ni)
#pragma unroll
            for (int q = 0; q < 4; ++q) c[mi][ni][q] = 0.f;

    for (int chunk = 0; chunk < 2; ++chunk) {
        int kp0 = chunk * 32;
        __syncthreads();
#pragma unroll
        for (int i = 0; i < 16; ++i) {
            int idx = i * 256 + tid;
            int r = idx >> 5, p = idx & 31;
            int gr = row0 + r;
            float2 v = (gr < nrows) ? load_pair<TIn>(X, (size_t)gr * 128 + (kp0 + p) * 2)
                                    : make_float2(0.f, 0.f);
            uint32_t h, l;
            cvt_hilo(v.x, v.y, h, l);
            Ahi[r * ASTR + p] = h;
            Alo[r * ASTR + p] = l;
            Bhi[r * ASTR + p] = Wthi[r * 64 + kp0 + p];
            Blo[r * ASTR + p] = Wtlo[r * 64 + kp0 + p];
        }
        __syncthreads();

        const int aB0 = (wm * 32 + g) * ASTR + tig;
        const int bB0 = (wn * 64 + g) * ASTR + tig;
#pragma unroll
        for (int ks = 0; ks < 4; ++ks) {
            int pb = ks * 8;
            uint32_t ah[2][4], al[2][4];
#pragma unroll
            for (int mi = 0; mi < 2; ++mi) {
                int ab = aB0 + mi * 16 * ASTR + pb;
                ah[mi][0] = Ahi[ab];
                ah[mi][1] = Ahi[ab + 8 * ASTR];
                ah[mi][2] = Ahi[ab + 4];
                ah[mi][3] = Ahi[ab + 8 * ASTR + 4];
                al[mi][0] = Alo[ab];
                al[mi][1] = Alo[ab + 8 * ASTR];
                al[mi][2] = Alo[ab + 4];
                al[mi][3] = Alo[ab + 8 * ASTR + 4];
            }
#pragma unroll
            for (int ni = 0; ni < 8; ++ni) {
                int bb = bB0 + ni * 8 * ASTR + pb;
                uint32_t bh0 = Bhi[bb];
                uint32_t bh1 = Bhi[bb + 4];
                uint32_t bl0 = Blo[bb];
                uint32_t bl1 = Blo[bb + 4];
#pragma unroll
                for (int mi = 0; mi < 2; ++mi) {
                    MMA_BF16(c[mi][ni][0], c[mi][ni][1], c[mi][ni][2], c[mi][ni][3],
                             ah[mi][0], ah[mi][1], ah[mi][2], ah[mi][3], bh0, bh1);
                    MMA_BF16(c[mi][ni][0], c[mi][ni][1], c[mi][ni][2], c[mi][ni][3],
                             ah[mi][0], ah[mi][1], ah[mi][2], ah[mi][3], bl0, bl1);
                    MMA_BF16(c[mi][ni][0], c[mi][ni][1], c[mi][ni][2], c[mi][ni][3],
                             al[mi][0], al[mi][1], al[mi][2], al[mi][3], bh0, bh1);
                }
            }
        }
    }

#pragma unroll
    for (int mi = 0; mi < 2; ++mi) {
        int r = row0 + wm * 32 + mi * 16 + g;
#pragma unroll
        for (int ni = 0; ni < 8; ++ni) {
            int cn = wn * 64 + ni * 8 + 2 * tig;
            if (r < nrows)
                *(__half2*)&out[(size_t)r * 128 + cn] = __floats2half2_rn(c[mi][ni][0], c[mi][ni][1]);
            if (r + 8 < nrows)
                *(__half2*)&out[(size_t)(r + 8) * 128 + cn] = __floats2half2_rn(c[mi][ni][2], c[mi][ni][3]);
        }
    }
}

// ==== CSR gather (fp16 source) -> fp16 out + fused attention partial ====
__device__ __forceinline__ void acc_row(float4& acc, const __half* __restrict__ S,
                                        int s, int lane, float w)
{
    uint2 u = ((const uint2*)(S + (size_t)s * 128))[lane];
    __half2 p0 = *(__half2*)&u.x;
    __half2 p1 = *(__half2*)&u.y;
    float2 f0 = __half22float2(p0);
    float2 f1 = __half22float2(p1);
    acc.x = fmaf(w, f0.x, acc.x);
    acc.y = fmaf(w, f0.y, acc.y);
    acc.z = fmaf(w, f1.x, acc.z);
    acc.w = fmaf(w, f1.y, acc.w);
}

__global__ __launch_bounds__(256) void gather_relu(const int* __restrict__ rowptr,
                                                   const int* __restrict__ esrc,
                                                   const float* __restrict__ ews,
                                                   const __half* __restrict__ S,
                                                   const float* __restrict__ b,
                                                   const float* __restrict__ wa_seg,
                                                   __half* __restrict__ out,
                                                   float* __restrict__ T,
                                                   int accum)
{
    int gt   = blockIdx.x * blockDim.x + threadIdx.x;
    int node = gt >> 5;
    int lane = gt & 31;
    if (node >= N_NODES) return;

    int e0 = rowptr[node], e1 = rowptr[node + 1];
    float4 acc = make_float4(0.f, 0.f, 0.f, 0.f);

    int e = e0;
    for (; e + 3 < e1; e += 4) {
        int   s0 = __ldg(esrc + e),     s1 = __ldg(esrc + e + 1);
        int   s2 = __ldg(esrc + e + 2), s3 = __ldg(esrc + e + 3);
        float w0 = __ldg(ews + e),      w1 = __ldg(ews + e + 1);
        float w2 = __ldg(ews + e + 2),  w3 = __ldg(ews + e + 3);
        acc_row(acc, S, s0, lane, w0);
        acc_row(acc, S, s1, lane, w1);
        acc_row(acc, S, s2, lane, w2);
        acc_row(acc, S, s3, lane, w3);
    }
    for (; e < e1; ++e) {
        int   s0 = __ldg(esrc + e);
        float w0 = __ldg(ews + e);
        acc_row(acc, S, s0, lane, w0);
    }

    float4 bb = ((const float4*)b)[lane];
    acc.x = fmaxf(acc.x + bb.x, 0.f);
    acc.y = fmaxf(acc.y + bb.y, 0.f);
    acc.z = fmaxf(acc.z + bb.z, 0.f);
    acc.w = fmaxf(acc.w + bb.w, 0.f);

    uint2 st;
    *(__half2*)&st.x = __floats2half2_rn(acc.x, acc.y);
    *(__half2*)&st.y = __floats2half2_rn(acc.z, acc.w);
    ((uint2*)(out + (size_t)node * 128))[lane] = st;

    float4 ww = ((const float4*)wa_seg)[lane];
    float s = acc.x * ww.x + acc.y * ww.y + acc.z * ww.z + acc.w * ww.w;
#pragma unroll
    for (int off = 16; off; off >>= 1) s += __shfl_xor_sync(0xFFFFFFFFu, s, off);
    if (lane == 0) {
        if (accum) T[node] += s;
        else       T[node]  = s;
    }
}

// ---------- sc[node] = tanh( sum_e w_e * t[esrc[e]] + ba ) ----------
__global__ __launch_bounds__(256) void gather_score(const int* __restrict__ rowptr,
                                                    const int* __restrict__ esrc,
                                                    const float* __restrict__ ews,
                                                    const float* __restrict__ t,
                                                    const float* __restrict__ ba,
                                                    float* __restrict__ sc)
{
    int gt   = blockIdx.x * blockDim.x + threadIdx.x;
    int node = gt >> 5;
    int lane = gt & 31;
    if (node >= N_NODES) return;

    int e0 = rowptr[node], e1 = rowptr[node + 1];
    float s = 0.f;
    for (int e = e0 + lane; e < e1; e += 32)
        s = fmaf(__ldg(ews + e), __ldg(t + __ldg(esrc + e)), s);
#pragma unroll
    for (int off = 16; off; off >>= 1) s += __shfl_xor_sync(0xFFFFFFFFu, s, off);
    if (lane == 0) sc[node] = tanhf(s + ba[0]);
}

// ---------------- per-graph pooling (fp16 G) ----------------
__device__ __forceinline__ int lowerb(const int* a, int n, int v)
{
    int lo = 0, hi = n;
    while (lo < hi) { int m = (lo + hi) >> 1; if (a[m] < v) lo = m + 1; else hi = m; }
    return lo;
}

__global__ __launch_bounds__(384) void pool_part(const __half* __restrict__ g1,
                                                 const __half* __restrict__ g2,
                                                 const __half* __restrict__ g3,
                                                 const float* __restrict__ score,
                                                 const int* __restrict__ gi,
                                                 float* __restrict__ pps,
                                                 float* __restrict__ ppm,
                                                 int* __restrict__ gcnt)
{
    int b = blockIdx.x;
    int g = b >> 2, part = b & 3;
    int c = threadIdx.x;
    __shared__ int sS, sE;
    if (c == 0) sS = lowerb(gi, N_NODES, g);
    if (c == 1) sE = lowerb(gi, N_NODES, g + 1);
    __syncthreads();
    int start = sS, end = sE, len = end - start;
    int n0 = start + (len * part) / 4;
    int n1 = start + (len * (part + 1)) / 4;

    const __half* base = (c < 128) ? g1 : (c < 256) ? g2 : g3;
    int cc = c & 127;

    float sum = 0.f, mx = -INFINITY;
    for (int n = n0; n < n1; ++n) {
        float v = __half2float(base[(size_t)n * 128 + cc]) * score[n];
        sum += v;
        mx = fmaxf(mx, v);
    }
    pps[b * 384 + c] = sum;
    ppm[b * 384 + c] = mx;
    if (part == 0 && c == 0) gcnt[g] = len;
}

__global__ __launch_bounds__(384) void pool_comb(const float* __restrict__ pps,
                                                 const float* __restrict__ ppm,
                                                 const int* __restrict__ gcnt,
                                                 float* __restrict__ pooled)
{
    int g = blockIdx.x, c = threadIdx.x;
    float sum = 0.f, mx = -INFINITY;
#pragma unroll
    for (int p = 0; p < 4; ++p) {
        sum += pps[(g * 4 + p) * 384 + c];
        mx = fmaxf(mx, ppm[(g * 4 + p) * 384 + c]);
    }
    float cnt = (float)gcnt[g];
    pooled[g * 768 + c]       = sum / fmaxf(cnt, 1.f);
    pooled[g * 768 + 384 + c] = mx;
}

// ---------------- out = relu(pooled @ Wf + bf) ----------------
__global__ __launch_bounds__(128) void final_k(const float* __restrict__ pooled,
                                               const float* __restrict__ Wf,
                                               const float* __restrict__ bf,
                                               float* __restrict__ out)
{
    int g = blockIdx.x, c = threadIdx.x;
    __shared__ float pr[768];
    for (int i = c; i < 768; i += 128) pr[i] = pooled[g * 768 + i];
    __syncthreads();
    float acc = bf[c];
#pragma unroll 8
    for (int k = 0; k < 768; ++k) acc = fmaf(pr[k], Wf[k * 128 + c], acc);
    out[g * 128 + c] = fmaxf(acc, 0.f);
}

// ---------------- launch ----------------
extern "C" void kernel_launch(void* const* d_in, const int* in_sizes, int n_in,
                              void* d_out, int out_size)
{
    const int*   ei  = (const int*)d_in[0];
    const float* ew  = (const float*)d_in[1];
    const float* X   = (const float*)d_in[2];
    const int*   gi  = (const int*)d_in[3];
    const float* W1  = (const float*)d_in[4];
    const float* b1  = (const float*)d_in[5];
    const float* W2  = (const float*)d_in[6];
    const float* b2  = (const float*)d_in[7];
    const float* W3  = (const float*)d_in[8];
    const float* b3  = (const float*)d_in[9];
    const float* wa  = (const float*)d_in[10];
    const float* ba  = (const float*)d_in[11];
    const float* Wf  = (const float*)d_in[12];
    const float* bf  = (const float*)d_in[13];
    float* out = (float*)d_out;

    const int* src = ei;
    const int* dst = ei + N_EDGES;

    static int inited = 0;
    static cudaStream_t s2;
    static cudaEvent_t evFork, evJoin;
    if (!inited) {
        cudaFuncSetAttribute(gemm_bf16x3<float>,  cudaFuncAttributeMaxDynamicSharedMemorySize, GEMM_SMEM);
        cudaFuncSetAttribute(gemm_bf16x3<__half>, cudaFuncAttributeMaxDynamicSharedMemorySize, GEMM_SMEM);
        cudaStreamCreateWithFlags(&s2, cudaStreamNonBlocking);
        cudaEventCreateWithFlags(&evFork, cudaEventDisableTiming);
        cudaEventCreateWithFlags(&evJoin, cudaEventDisableTiming);
        inited = 1;
    }

    void *pS, *pG1, *pG2, *pG3, *pT, *pSC, *pPOOL;
    void *pCNT, *pRP, *pCUR, *pESRC, *pEWS, *pPPS, *pPPM, *pGC, *pWH, *pWL;
    cudaGetSymbolAddress(&pS,   d_S16);
    cudaGetSymbolAddress(&pG1,  d_G1);
    cudaGetSymbolAddress(&pG2,  d_G2);
    cudaGetSymbolAddress(&pG3,  d_G3);
    cudaGetSymbolAddress(&pT,   d_T);
    cudaGetSymbolAddress(&pSC,  d_SC);
    cudaGetSymbolAddress(&pPOOL, d_POOL);
    cudaGetSymbolAddress(&pCNT, d_CNT);
    cudaGetSymbolAddress(&pRP,  d_ROWPTR);
    cudaGetSymbolAddress(&pCUR, d_CUR);
    cudaGetSymbolAddress(&pESRC, d_ESRC);
    cudaGetSymbolAddress(&pEWS,  d_EWS);
    cudaGetSymbolAddress(&pPPS, d_PPS);
    cudaGetSymbolAddress(&pPPM, d_PPM);
    cudaGetSymbolAddress(&pGC,  d_GCNT);
    cudaGetSymbolAddress(&pWH,  d_WH);
    cudaGetSymbolAddress(&pWL,  d_WL);

    __half* S  = (__half*)pS;
    __half* G1 = (__half*)pG1;
    __half* G2 = (__half*)pG2;
    __half* G3 = (__half*)pG3;
    float* T   = (float*)pT;
    float* SC  = (float*)pSC;
    float* PO  = (float*)pPOOL;
    int*   CNT = (int*)pCNT;
    int*   RP  = (int*)pRP;
    int*   CUR = (int*)pCUR;
    int*   ESRC = (int*)pESRC;
    float* EWS  = (float*)pEWS;
    float* PPS = (float*)pPPS;
    float* PPM = (float*)pPPM;
    int*   GC  = (int*)pGC;
    uint32_t* WH = (uint32_t*)pWH;
    uint32_t* WL = (uint32_t*)pWL;

    const int gemm_grid = (N_NODES + 127) / 128;
    const int edge_grid = (N_EDGES + 255) / 256;
    const int warp_grid = (N_NODES * 32 + 255) / 256;

    // ---- fork: CSR build on s2, concurrent with wprep + gemm1 on main ----
    cudaEventRecord(evFork, 0);
    cudaStreamWaitEvent(s2, evFork, 0);

    cudaMemsetAsync(CNT, 0, N_NODES * sizeof(int), s2);
    csr_count<<<edge_grid, 256, 0, s2>>>(dst, CNT);
    csr_scan<<<1, 1024, 0, s2>>>(CNT, RP, CUR);
    csr_fill<<<edge_grid, 256, 0, s2>>>(src, dst, ew, CUR, ESRC, EWS);
    cudaEventRecord(evJoin, s2);

    // ---- main stream: W conversion + gemm1 ----
    wprep<<<32, 256>>>(W1, WH,          WL);
    wprep<<<32, 256>>>(W2, WH + 8192,   WL + 8192);
    wprep<<<32, 256>>>(W3, WH + 16384,  WL + 16384);
    gemm_bf16x3<float><<<gemm_grid, 256, GEMM_SMEM>>>(X, WH, WL, S, N_NODES);

    // ---- join: gathers need CSR ----
    cudaStreamWaitEvent(0, evJoin, 0);

    gather_relu<<<warp_grid, 256>>>(RP, ESRC, EWS, S, b1, wa,       G1, T, 0);
    gemm_bf16x3<__half><<<gemm_grid, 256, GEMM_SMEM>>>(G1, WH + 8192, WL + 8192, S, N_NODES);
    gather_relu<<<warp_grid, 256>>>(RP, ESRC, EWS, S, b2, wa + 128, G2, T, 1);
    gemm_bf16x3<__half><<<gemm_grid, 256, GEMM_SMEM>>>(G2, WH + 16384, WL + 16384, S, N_NODES);
    gather_relu<<<warp_grid, 256>>>(RP, ESRC, EWS, S, b3, wa + 256, G3, T, 1);

    // ---- attention score ----
    gather_score<<<warp_grid, 256>>>(RP, ESRC, EWS, T, ba, SC);

    // ---- pooling + final FC ----
    pool_part<<<N_GRAPHS * 4, 384>>>(G1, G2, G3, SC, gi, PPS, PPM, GC);
    pool_comb<<<N_GRAPHS, 384>>>(PPS, PPM, GC, PO);
    final_k<<<N_GRAPHS, 128>>>(PO, Wf, bf, out);

    (void)in_sizes; (void)n_in; (void)out_size;
}

// round 12
// speedup vs baseline: 2.3795x; 1.0391x over previous
#include <cuda_runtime.h>
#include <cuda_bf16.h>
#include <cuda_fp16.h>
#include <math.h>
#include <stdint.h>

#define N_NODES 50000
#define N_EDGES 800000
#define HID     128
#define N_GRAPHS 64

// ---------------- scratch (allocation-free: __device__ globals) ----------------
__device__ __half d_S16[N_NODES * HID];   // GEMM output (gather source), fp16
__device__ __half d_G1[N_NODES * HID];    // layer outputs, fp16
__device__ __half d_G2[N_NODES * HID];
__device__ __half d_G3[N_NODES * HID];
__device__ float d_T [N_NODES];
__device__ float d_SC[N_NODES];
__device__ float d_POOL[N_GRAPHS * 6 * HID];
// CSR scratch
__device__ int   d_CNT[N_NODES];
__device__ int   d_ROWPTR[N_NODES + 1];
__device__ int   d_CUR[N_NODES];
__device__ int2  d_EDGE[N_EDGES];         // {src, weight bits} packed
// pooling partials
__device__ float d_PPS[N_GRAPHS * 4 * 384];
__device__ float d_PPM[N_GRAPHS * 4 * 384];
__device__ int   d_GCNT[N_GRAPHS];
// W converted: transposed [n][kpair] packed fp16x2, hi/lo, 3 layers
__device__ uint32_t d_WH[3][128 * 64];
__device__ uint32_t d_WL[3][128 * 64];

// ---- fp16 hi/lo split + pack ----
__device__ __forceinline__ uint32_t packh2(__half a, __half b)
{
    __half2 h = __halves2half2(a, b);
    return *(uint32_t*)&h;
}
__device__ __forceinline__ void cvt_hilo16(float x, float y, uint32_t& hi, uint32_t& lo)
{
    __half h0 = __float2half_rn(x);
    __half h1 = __float2half_rn(y);
    float rx = x - __half2float(h0);
    float ry = y - __half2float(h1);
    hi = packh2(h0, h1);
    lo = packh2(__float2half_rn(rx), __float2half_rn(ry));
}

#define MMA_F16(c0,c1,c2,c3, a0,a1,a2,a3, b0,b1) \
    asm("mma.sync.aligned.m16n8k16.row.col.f32.f16.f16.f32 " \
        "{%0,%1,%2,%3}, {%4,%5,%6,%7}, {%8,%9}, {%0,%1,%2,%3};" \
        : "+f"(c0), "+f"(c1), "+f"(c2), "+f"(c3) \
        : "r"(a0), "r"(a1), "r"(a2), "r"(a3), "r"(b0), "r"(b1))

// ================= W prep (all 3 layers): W[k][n] fp32 -> Wt[n][kpair] fp16 hi/lo =================
__global__ __launch_bounds__(256) void wprep3(const float* __restrict__ W1,
                                              const float* __restrict__ W2,
                                              const float* __restrict__ W3,
                                              uint32_t* __restrict__ hi,
                                              uint32_t* __restrict__ lo)
{
    int idx = blockIdx.x * blockDim.x + threadIdx.x;   // 0..24575
    if (idx >= 3 * 128 * 64) return;
    int layer = idx >> 13;
    int r     = idx & 8191;
    const float* W = (layer == 0) ? W1 : (layer == 1) ? W2 : W3;
    int n = r >> 6, p = r & 63;
    float w0 = W[(2 * p) * 128 + n];
    float w1 = W[(2 * p + 1) * 128 + n];
    uint32_t h, l;
    cvt_hilo16(w0, w1, h, l);
    hi[idx] = h;
    lo[idx] = l;
}

// ================= CSR build =================
__global__ __launch_bounds__(256) void csr_count(const int* __restrict__ dst, int* __restrict__ cnt)
{
    int e = blockIdx.x * blockDim.x + threadIdx.x;
    if (e < N_EDGES) atomicAdd(&cnt[dst[e]], 1);
}

__global__ __launch_bounds__(1024) void csr_scan(const int* __restrict__ cnt,
                                                 int* __restrict__ rowptr,
                                                 int* __restrict__ cur)
{
    __shared__ int warpsum[32];
    __shared__ int carry;
    int t = threadIdx.x, lane = t & 31, w = t >> 5;
    if (t == 0) carry = 0;
    __syncthreads();
    for (int base = 0; base < N_NODES; base += 1024) {
        int i = base + t;
        int v = (i < N_NODES) ? cnt[i] : 0;
        int x = v;
#pragma unroll
        for (int off = 1; off < 32; off <<= 1) {
            int y = __shfl_up_sync(0xFFFFFFFFu, x, off);
            if (lane >= off) x += y;
        }
        if (lane == 31) warpsum[w] = x;
        __syncthreads();
        if (w == 0) {
            int s = warpsum[lane];
#pragma unroll
            for (int off = 1; off < 32; off <<= 1) {
                int y = __shfl_up_sync(0xFFFFFFFFu, s, off);
                if (lane >= off) s += y;
            }
            warpsum[lane] = s;
        }
        __syncthreads();
        int incl = x + (w > 0 ? warpsum[w - 1] : 0);
        if (i < N_NODES) {
            int ex = carry + incl - v;
            rowptr[i] = ex;
            cur[i]    = ex;
        }
        __syncthreads();
        if (t == 1023) carry += warpsum[31];
        __syncthreads();
    }
    if (t == 0) rowptr[N_NODES] = carry;
}

__global__ __launch_bounds__(256) void csr_fill(const int* __restrict__ src,
                                                const int* __restrict__ dst,
                                                const float* __restrict__ ew,
                                                int* __restrict__ cur,
                                                int2* __restrict__ edge)
{
    int e = blockIdx.x * blockDim.x + threadIdx.x;
    if (e >= N_EDGES) return;
    int d = dst[e];
    int p = atomicAdd(&cur[d], 1);
    edge[p] = make_int2(src[e], __float_as_int(ew[e]));
}

// ===== GEMM via fp16 tensor cores =====
// out = X @ W ; W = Whi + Wlo (fp16 split).
// SPLIT_A (layer 1, fp32 X): A = Ahi + Alo fp16 split, 3 MMAs.
// !SPLIT_A (layers 2/3, fp16 G): A exact fp16, 2 MMAs.
#define ASTR 36
#define SM_CH (128 * ASTR)
#define GEMM_SMEM (4 * SM_CH * 4)

template <typename TIn, bool SPLIT_A>
__global__ __launch_bounds__(256, 2) void gemm_f16(const TIn* __restrict__ X,
                                                   const uint32_t* __restrict__ Wthi,
                                                   const uint32_t* __restrict__ Wtlo,
                                                   __half* __restrict__ out, int nrows)
{
    extern __shared__ uint32_t sm[];
    uint32_t* Ahi = sm;
    uint32_t* Alo = sm + SM_CH;
    uint32_t* Bhi = sm + 2 * SM_CH;
    uint32_t* Blo = sm + 3 * SM_CH;

    const int tid  = threadIdx.x;
    const int row0 = blockIdx.x * 128;
    const int warp = tid >> 5, lane = tid & 31;
    const int g    = lane >> 2, tig = lane & 3;
    const int wm   = warp >> 1, wn = warp & 1;

    float c[2][8][4];
#pragma unroll
    for (int mi = 0; mi < 2; ++mi)
#pragma unroll
        for (int ni = 0; ni < 8; ++ni)
#pragma unroll
            for (int q = 0; q < 4; ++q) c[mi][ni][q] = 0.f;

    for (int chunk = 0; chunk < 2; ++chunk) {
        int kp0 = chunk * 32;
        __syncthreads();
#pragma unroll
        for (int i = 0; i < 16; ++i) {
            int idx = i * 256 + tid;
            int r = idx >> 5, p = idx & 31;
            int gr = row0 + r;
            if (SPLIT_A) {
                float2 v = (gr < nrows)
                    ? *(const float2*)((const float*)X + (size_t)gr * 128 + (kp0 + p) * 2)
                    : make_float2(0.f, 0.f);
                uint32_t h, l;
                cvt_hilo16(v.x, v.y, h, l);
                Ahi[r * ASTR + p] = h;
                Alo[r * ASTR + p] = l;
            } else {
                uint32_t h = (gr < nrows)
                    ? *(const uint32_t*)((const __half*)X + (size_t)gr * 128 + (kp0 + p) * 2)
                    : 0u;
                Ahi[r * ASTR + p] = h;
            }
            Bhi[r * ASTR + p] = Wthi[r * 64 + kp0 + p];
            Blo[r * ASTR + p] = Wtlo[r * 64 + kp0 + p];
        }
        __syncthreads();

        const int aB0 = (wm * 32 + g) * ASTR + tig;
        const int bB0 = (wn * 64 + g) * ASTR + tig;
#pragma unroll
        for (int ks = 0; ks < 4; ++ks) {
            int pb = ks * 8;
            uint32_t ah[2][4], al[2][4];
#pragma unroll
            for (int mi = 0; mi < 2; ++mi) {
                int ab = aB0 + mi * 16 * ASTR + pb;
                ah[mi][0] = Ahi[ab];
                ah[mi][1] = Ahi[ab + 8 * ASTR];
                ah[mi][2] = Ahi[ab + 4];
                ah[mi][3] = Ahi[ab + 8 * ASTR + 4];
                if (SPLIT_A) {
                    al[mi][0] = Alo[ab];
                    al[mi][1] = Alo[ab + 8 * ASTR];
                    al[mi][2] = Alo[ab + 4];
                    al[mi][3] = Alo[ab + 8 * ASTR + 4];
                }
            }
#pragma unroll
            for (int ni = 0; ni < 8; ++ni) {
                int bb = bB0 + ni * 8 * ASTR + pb;
                uint32_t bh0 = Bhi[bb];
                uint32_t bh1 = Bhi[bb + 4];
                uint32_t bl0 = Blo[bb];
                uint32_t bl1 = Blo[bb + 4];
#pragma unroll
                for (int mi = 0; mi < 2; ++mi) {
                    MMA_F16(c[mi][ni][0], c[mi][ni][1], c[mi][ni][2], c[mi][ni][3],
                            ah[mi][0], ah[mi][1], ah[mi][2], ah[mi][3], bh0, bh1);
                    MMA_F16(c[mi][ni][0], c[mi][ni][1], c[mi][ni][2], c[mi][ni][3],
                            ah[mi][0], ah[mi][1], ah[mi][2], ah[mi][3], bl0, bl1);
                    if (SPLIT_A)
                        MMA_F16(c[mi][ni][0], c[mi][ni][1], c[mi][ni][2], c[mi][ni][3],
                                al[mi][0], al[mi][1], al[mi][2], al[mi][3], bh0, bh1);
                }
            }
        }
    }

#pragma unroll
    for (int mi = 0; mi < 2; ++mi) {
        int r = row0 + wm * 32 + mi * 16 + g;
#pragma unroll
        for (int ni = 0; ni < 8; ++ni) {
            int cn = wn * 64 + ni * 8 + 2 * tig;
            if (r < nrows)
                *(__half2*)&out[(size_t)r * 128 + cn] = __floats2half2_rn(c[mi][ni][0], c[mi][ni][1]);
            if (r + 8 < nrows)
                *(__half2*)&out[(size_t)(r + 8) * 128 + cn] = __floats2half2_rn(c[mi][ni][2], c[mi][ni][3]);
        }
    }
}

// ==== CSR gather (fp16 source, packed edges) -> fp16 out + fused attention partial ====
__device__ __forceinline__ void acc_row(float4& acc, const __half* __restrict__ S,
                                        int s, int lane, float w)
{
    uint2 u = ((const uint2*)(S + (size_t)s * 128))[lane];
    __half2 p0 = *(__half2*)&u.x;
    __half2 p1 = *(__half2*)&u.y;
    float2 f0 = __half22float2(p0);
    float2 f1 = __half22float2(p1);
    acc.x = fmaf(w, f0.x, acc.x);
    acc.y = fmaf(w, f0.y, acc.y);
    acc.z = fmaf(w, f1.x, acc.z);
    acc.w = fmaf(w, f1.y, acc.w);
}

__global__ __launch_bounds__(256) void gather_relu(const int* __restrict__ rowptr,
                                                   const int2* __restrict__ edge,
                                                   const __half* __restrict__ S,
                                                   const float* __restrict__ b,
                                                   const float* __restrict__ wa_seg,
                                                   __half* __restrict__ out,
                                                   float* __restrict__ T,
                                                   int accum)
{
    int gt   = blockIdx.x * blockDim.x + threadIdx.x;
    int node = gt >> 5;
    int lane = gt & 31;
    if (node >= N_NODES) return;

    int e0 = rowptr[node], e1 = rowptr[node + 1];
    float4 acc = make_float4(0.f, 0.f, 0.f, 0.f);

    int e = e0;
    for (; e + 3 < e1; e += 4) {
        int2 d0 = __ldg(edge + e);
        int2 d1 = __ldg(edge + e + 1);
        int2 d2 = __ldg(edge + e + 2);
        int2 d3 = __ldg(edge + e + 3);
        acc_row(acc, S, d0.x, lane, __int_as_float(d0.y));
        acc_row(acc, S, d1.x, lane, __int_as_float(d1.y));
        acc_row(acc, S, d2.x, lane, __int_as_float(d2.y));
        acc_row(acc, S, d3.x, lane, __int_as_float(d3.y));
    }
    for (; e < e1; ++e) {
        int2 d0 = __ldg(edge + e);
        acc_row(acc, S, d0.x, lane, __int_as_float(d0.y));
    }

    float4 bb = ((const float4*)b)[lane];
    acc.x = fmaxf(acc.x + bb.x, 0.f);
    acc.y = fmaxf(acc.y + bb.y, 0.f);
    acc.z = fmaxf(acc.z + bb.z, 0.f);
    acc.w = fmaxf(acc.w + bb.w, 0.f);

    uint2 st;
    *(__half2*)&st.x = __floats2half2_rn(acc.x, acc.y);
    *(__half2*)&st.y = __floats2half2_rn(acc.z, acc.w);
    ((uint2*)(out + (size_t)node * 128))[lane] = st;

    float4 ww = ((const float4*)wa_seg)[lane];
    float s = acc.x * ww.x + acc.y * ww.y + acc.z * ww.z + acc.w * ww.w;
#pragma unroll
    for (int off = 16; off; off >>= 1) s += __shfl_xor_sync(0xFFFFFFFFu, s, off);
    if (lane == 0) {
        if (accum) T[node] += s;
        else       T[node]  = s;
    }
}

// ---------- sc[node] = tanh( sum_e w_e * t[src_e] + ba ) ----------
__global__ __launch_bounds__(256) void gather_score(const int* __restrict__ rowptr,
                                                    const int2* __restrict__ edge,
                                                    const float* __restrict__ t,
                                                    const float* __restrict__ ba,
                                                    float* __restrict__ sc)
{
    int gt   = blockIdx.x * blockDim.x + threadIdx.x;
    int node = gt >> 5;
    int lane = gt & 31;
    if (node >= N_NODES) return;

    int e0 = rowptr[node], e1 = rowptr[node + 1];
    float s = 0.f;
    for (int e = e0 + lane; e < e1; e += 32) {
        int2 d = __ldg(edge + e);
        s = fmaf(__int_as_float(d.y), __ldg(t + d.x), s);
    }
#pragma unroll
    for (int off = 16; off; off >>= 1) s += __shfl_xor_sync(0xFFFFFFFFu, s, off);
    if (lane == 0) sc[node] = tanhf(s + ba[0]);
}

// ---------------- per-graph pooling (fp16 G) ----------------
__device__ __forceinline__ int lowerb(const int* a, int n, int v)
{
    int lo = 0, hi = n;
    while (lo < hi) { int m = (lo + hi) >> 1; if (a[m] < v) lo = m + 1; else hi = m; }
    return lo;
}

__global__ __launch_bounds__(384) void pool_part(const __half* __restrict__ g1,
                                                 const __half* __restrict__ g2,
                                                 const __half* __restrict__ g3,
                                                 const float* __restrict__ score,
                                                 const int* __restrict__ gi,
                                                 float* __restrict__ pps,
                                                 float* __restrict__ ppm,
                                                 int* __restrict__ gcnt)
{
    int b = blockIdx.x;
    int g = b >> 2, part = b & 3;
    int c = threadIdx.x;
    __shared__ int sS, sE;
    if (c == 0) sS = lowerb(gi, N_NODES, g);
    if (c == 1) sE = lowerb(gi, N_NODES, g + 1);
    __syncthreads();
    int start = sS, end = sE, len = end - start;
    int n0 = start + (len * part) / 4;
    int n1 = start + (len * (part + 1)) / 4;

    const __half* base = (c < 128) ? g1 : (c < 256) ? g2 : g3;
    int cc = c & 127;

    float sum = 0.f, mx = -INFINITY;
    for (int n = n0; n < n1; ++n) {
        float v = __half2float(base[(size_t)n * 128 + cc]) * score[n];
        sum += v;
        mx = fmaxf(mx, v);
    }
    pps[b * 384 + c] = sum;
    ppm[b * 384 + c] = mx;
    if (part == 0 && c == 0) gcnt[g] = len;
}

__global__ __launch_bounds__(384) void pool_comb(const float* __restrict__ pps,
                                                 const float* __restrict__ ppm,
                                                 const int* __restrict__ gcnt,
                                                 float* __restrict__ pooled)
{
    int g = blockIdx.x, c = threadIdx.x;
    float sum = 0.f, mx = -INFINITY;
#pragma unroll
    for (int p = 0; p < 4; ++p) {
        sum += pps[(g * 4 + p) * 384 + c];
        mx = fmaxf(mx, ppm[(g * 4 + p) * 384 + c]);
    }
    float cnt = (float)gcnt[g];
    pooled[g * 768 + c]       = sum / fmaxf(cnt, 1.f);
    pooled[g * 768 + 384 + c] = mx;
}

// ---------------- out = relu(pooled @ Wf + bf) ----------------
__global__ __launch_bounds__(128) void final_k(const float* __restrict__ pooled,
                                               const float* __restrict__ Wf,
                                               const float* __restrict__ bf,
                                               float* __restrict__ out)
{
    int g = blockIdx.x, c = threadIdx.x;
    __shared__ float pr[768];
    for (int i = c; i < 768; i += 128) pr[i] = pooled[g * 768 + i];
    __syncthreads();
    float acc = bf[c];
#pragma unroll 8
    for (int k = 0; k < 768; ++k) acc = fmaf(pr[k], Wf[k * 128 + c], acc);
    out[g * 128 + c] = fmaxf(acc, 0.f);
}

// ---------------- launch ----------------
extern "C" void kernel_launch(void* const* d_in, const int* in_sizes, int n_in,
                              void* d_out, int out_size)
{
    const int*   ei  = (const int*)d_in[0];
    const float* ew  = (const float*)d_in[1];
    const float* X   = (const float*)d_in[2];
    const int*   gi  = (const int*)d_in[3];
    const float* W1  = (const float*)d_in[4];
    const float* b1  = (const float*)d_in[5];
    const float* W2  = (const float*)d_in[6];
    const float* b2  = (const float*)d_in[7];
    const float* W3  = (const float*)d_in[8];
    const float* b3  = (const float*)d_in[9];
    const float* wa  = (const float*)d_in[10];
    const float* ba  = (const float*)d_in[11];
    const float* Wf  = (const float*)d_in[12];
    const float* bf  = (const float*)d_in[13];
    float* out = (float*)d_out;

    const int* src = ei;
    const int* dst = ei + N_EDGES;

    static int inited = 0;
    static cudaStream_t s2;
    static cudaEvent_t evFork, evJoin;
    if (!inited) {
        cudaFuncSetAttribute(gemm_f16<float, true>,   cudaFuncAttributeMaxDynamicSharedMemorySize, GEMM_SMEM);
        cudaFuncSetAttribute(gemm_f16<__half, false>, cudaFuncAttributeMaxDynamicSharedMemorySize, GEMM_SMEM);
        cudaStreamCreateWithFlags(&s2, cudaStreamNonBlocking);
        cudaEventCreateWithFlags(&evFork, cudaEventDisableTiming);
        cudaEventCreateWithFlags(&evJoin, cudaEventDisableTiming);
        inited = 1;
    }

    void *pS, *pG1, *pG2, *pG3, *pT, *pSC, *pPOOL;
    void *pCNT, *pRP, *pCUR, *pEDGE, *pPPS, *pPPM, *pGC, *pWH, *pWL;
    cudaGetSymbolAddress(&pS,   d_S16);
    cudaGetSymbolAddress(&pG1,  d_G1);
    cudaGetSymbolAddress(&pG2,  d_G2);
    cudaGetSymbolAddress(&pG3,  d_G3);
    cudaGetSymbolAddress(&pT,   d_T);
    cudaGetSymbolAddress(&pSC,  d_SC);
    cudaGetSymbolAddress(&pPOOL, d_POOL);
    cudaGetSymbolAddress(&pCNT, d_CNT);
    cudaGetSymbolAddress(&pRP,  d_ROWPTR);
    cudaGetSymbolAddress(&pCUR, d_CUR);
    cudaGetSymbolAddress(&pEDGE, d_EDGE);
    cudaGetSymbolAddress(&pPPS, d_PPS);
    cudaGetSymbolAddress(&pPPM, d_PPM);
    cudaGetSymbolAddress(&pGC,  d_GCNT);
    cudaGetSymbolAddress(&pWH,  d_WH);
    cudaGetSymbolAddress(&pWL,  d_WL);

    __half* S  = (__half*)pS;
    __half* G1 = (__half*)pG1;
    __half* G2 = (__half*)pG2;
    __half* G3 = (__half*)pG3;
    float* T   = (float*)pT;
    float* SC  = (float*)pSC;
    float* PO  = (float*)pPOOL;
    int*   CNT = (int*)pCNT;
    int*   RP  = (int*)pRP;
    int*   CUR = (int*)pCUR;
    int2*  EDGE = (int2*)pEDGE;
    float* PPS = (float*)pPPS;
    float* PPM = (float*)pPPM;
    int*   GC  = (int*)pGC;
    uint32_t* WH = (uint32_t*)pWH;
    uint32_t* WL = (uint32_t*)pWL;

    const int gemm_grid = (N_NODES + 127) / 128;
    const int edge_grid = (N_EDGES + 255) / 256;
    const int warp_grid = (N_NODES * 32 + 255) / 256;

    // ---- fork: CSR build on s2, concurrent with wprep + gemm1 on main ----
    cudaEventRecord(evFork, 0);
    cudaStreamWaitEvent(s2, evFork, 0);

    cudaMemsetAsync(CNT, 0, N_NODES * sizeof(int), s2);
    csr_count<<<edge_grid, 256, 0, s2>>>(dst, CNT);
    csr_scan<<<1, 1024, 0, s2>>>(CNT, RP, CUR);
    csr_fill<<<edge_grid, 256, 0, s2>>>(src, dst, ew, CUR, EDGE);
    cudaEventRecord(evJoin, s2);

    // ---- main stream: W conversion + gemm1 ----
    wprep3<<<96, 256>>>(W1, W2, W3, WH, WL);
    gemm_f16<float, true><<<gemm_grid, 256, GEMM_SMEM>>>(X, WH, WL, S, N_NODES);

    // ---- join: gathers need CSR ----
    cudaStreamWaitEvent(0, evJoin, 0);

    gather_relu<<<warp_grid, 256>>>(RP, EDGE, S, b1, wa,       G1, T, 0);
    gemm_f16<__half, false><<<gemm_grid, 256, GEMM_SMEM>>>(G1, WH + 8192, WL + 8192, S, N_NODES);
    gather_relu<<<warp_grid, 256>>>(RP, EDGE, S, b2, wa + 128, G2, T, 1);
    gemm_f16<__half, false><<<gemm_grid, 256, GEMM_SMEM>>>(G2, WH + 16384, WL + 16384, S, N_NODES);
    gather_relu<<<warp_grid, 256>>>(RP, EDGE, S, b3, wa + 256, G3, T, 1);

    // ---- attention score ----
    gather_score<<<warp_grid, 256>>>(RP, EDGE, T, ba, SC);

    // ---- pooling + final FC ----
    pool_part<<<N_GRAPHS * 4, 384>>>(G1, G2, G3, SC, gi, PPS, PPM, GC);
    pool_comb<<<N_GRAPHS, 384>>>(PPS, PPM, GC, PO);
    final_k<<<N_GRAPHS, 128>>>(PO, Wf, bf, out);

    (void)in_sizes; (void)n_in; (void)out_size;
}